// round 7
// baseline (speedup 1.0000x reference)
#include <cuda_runtime.h>
#include <math.h>

#define BB 8
#define NN 2048
#define KK 32

// ---------------- scratch (device globals; no allocations) ----------------
__device__ float  g_big[BB*NN*NN];     // 134MB: G_hi (knn) / energy / attn / e-values
__device__ float  g_glo[BB*NN*NN];     // 134MB: G_lo (df tail for knn)
__device__ int    g_idx[BB*NN*KK];
__device__ float  g_xt [BB*NN*3];
__device__ float  g_xx [BB*NN];
__device__ float  g_Wa1[3*64],  g_Wb1[3*64];    // transposed [c][o]
__device__ float  g_Wa2[64*64], g_Wb2[64*64];
__device__ float  g_m1t[BB*NN*64];
__device__ float  g_f1t[BB*NN*64];
__device__ float  g_feat[BB*128*NN];
__device__ float  g_cat [BB*512*NN];
__device__ float  g_xqt [BB*NN*32];
__device__ float  g_xk  [BB*32*NN];
__device__ float  g_cs  [BB*NN];
__device__ float  g_xr  [BB*128*NN];
__device__ float  g_tb  [BB*128*NN];
__device__ float  g_ub  [BB*128*NN];
__device__ float  g_fuse[BB*1024*NN];
__device__ float  g_gm  [BB*1024];
__device__ float  g_c0  [BB*512];
__device__ float  g_h1  [BB*512*NN];
__device__ float  g_h2  [BB*256*NN];
__device__ double g_part[64*128];
__device__ float  g_mean[1024];
__device__ float  g_sden[1024];   // sqrt(var + eps)

// ---------------- double-float helpers (error-free fp32 transforms) ----------------
__device__ __forceinline__ void twoSum(float a, float b, float& s, float& e){
    s = __fadd_rn(a,b);
    float bb = __fsub_rn(s,a);
    e = __fadd_rn(__fsub_rn(a, __fsub_rn(s,bb)), __fsub_rn(b,bb));
}
__device__ __forceinline__ void dfMac(float& hi, float& lo, float a, float b){
    float p = __fmul_rn(a,b);
    float e = fmaf(a,b,-p);          // exact product tail
    float s, err;
    twoSum(hi, p, s, err);
    lo = __fadd_rn(lo, __fadd_rn(err, e));
    float hi2 = __fadd_rn(s, lo);    // renormalize
    lo = __fsub_rn(lo, __fsub_rn(hi2, s));
    hi = hi2;
}
__device__ __forceinline__ void dfAddF(float& hi, float& lo, float f){
    float s, e;
    twoSum(hi, f, s, e);
    lo = __fadd_rn(lo, e);
    float hi2 = __fadd_rn(s, lo);
    lo = __fsub_rn(lo, __fsub_rn(hi2, s));
    hi = hi2;
}

// ---------------- generic tiled SGEMM (honest fp32, ascending-k fma) ----------------
#define TBM 128
#define TBN 128
#define TBK 16

__global__ void __launch_bounds__(256) sgemm_k(
    const float* __restrict__ A, int lda, long sA,
    const float* __restrict__ Bm, int ldb, long sB,
    float* __restrict__ C, int ldc, long sC,
    int M, int Nn, int Kd,
    const float* __restrict__ bias,
    const float* __restrict__ rowbias,   // per-batch [M]
    int transOut)
{
    __shared__ float As[TBK][TBM+4];
    __shared__ float Bs[TBK][TBN+4];
    int b = blockIdx.z;
    const float* Ab = A + (long)b*sA;
    const float* Bb = Bm + (long)b*sB;
    float* Cb = C + (long)b*sC;
    int m0 = blockIdx.y*TBM, n0 = blockIdx.x*TBN;
    int tid = threadIdx.x;
    int tx = tid & 15, ty = tid >> 4;

    float acc[8][8];
    #pragma unroll
    for (int i=0;i<8;i++)
        #pragma unroll
        for (int j=0;j<8;j++) acc[i][j]=0.f;

    int aRow = tid >> 1;
    int aCol0 = (tid & 1) * 8;
    int bRow = tid >> 4;
    int bCol0 = (tid & 15) * 8;

    for (int k0 = 0; k0 < Kd; k0 += TBK) {
        #pragma unroll
        for (int j = 0; j < 8; j++) {
            int m = aRow, k = aCol0 + j;
            float v = 0.f;
            if (m0+m < M && k0+k < Kd) v = Ab[(long)(m0+m)*lda + k0+k];
            As[k][m] = v;
        }
        #pragma unroll
        for (int j = 0; j < 8; j++) {
            int k = bRow, n = bCol0 + j;
            float v = 0.f;
            if (k0+k < Kd && n0+n < Nn) v = Bb[(long)(k0+k)*ldb + n0+n];
            Bs[k][n] = v;
        }
        __syncthreads();
        #pragma unroll
        for (int kk = 0; kk < TBK; kk++) {
            float4 a0 = *reinterpret_cast<const float4*>(&As[kk][ty*8]);
            float4 a1 = *reinterpret_cast<const float4*>(&As[kk][ty*8+4]);
            float4 b0 = *reinterpret_cast<const float4*>(&Bs[kk][tx*8]);
            float4 b1 = *reinterpret_cast<const float4*>(&Bs[kk][tx*8+4]);
            float ra[8] = {a0.x,a0.y,a0.z,a0.w,a1.x,a1.y,a1.z,a1.w};
            float rb[8] = {b0.x,b0.y,b0.z,b0.w,b1.x,b1.y,b1.z,b1.w};
            #pragma unroll
            for (int i=0;i<8;i++)
                #pragma unroll
                for (int j=0;j<8;j++)
                    acc[i][j] = fmaf(ra[i], rb[j], acc[i][j]);
        }
        __syncthreads();
    }
    #pragma unroll
    for (int i=0;i<8;i++){
        int row = m0 + ty*8 + i;
        if (row >= M) continue;
        float rb0 = 0.f;
        bool hasb = false;
        if (bias){    rb0 = __fadd_rn(rb0, bias[row]); hasb = true; }
        if (rowbias){ rb0 = __fadd_rn(rb0, rowbias[(long)b*M + row]); hasb = true; }
        #pragma unroll
        for (int j=0;j<8;j++){
            int col = n0 + tx*8 + j;
            if (col >= Nn) continue;
            float v = acc[i][j];
            if (hasb) v = __fadd_rn(v, rb0);
            if (!transOut) Cb[(long)row*ldc + col] = v;
            else           Cb[(long)col*ldc + row] = v;   // ldc == M
        }
    }
}

// ---------------- double-float Gram: G[n][m] = sum_c A[n][c]*B[c][m] (near-exact) ----------------
template<int C>
__global__ void __launch_bounds__(256) gram_df_t(
    const float* __restrict__ At, long sA,   // [B][NN][C]  n-major
    const float* __restrict__ Bc, long sB,   // [B][>=C][NN] c-major, ldb=NN
    float* __restrict__ Ghi, float* __restrict__ Glo)
{
    __shared__ float As[64][(C==3)?3:65];
    __shared__ float Bs[C][65];
    int b = blockIdx.z;
    int n0 = blockIdx.y*64, m0 = blockIdx.x*64;
    int t = threadIdx.x;
    const float* Ab = At + (long)b*sA;
    const float* Bb = Bc + (long)b*sB;
    for (int i=t; i<64*C; i+=256){ int n=i/C, c=i-n*C; As[n][c] = Ab[(long)(n0+n)*C + c]; }
    for (int i=t; i<C*64; i+=256){ int c=i>>6, m=i&63;  Bs[c][m] = Bb[(long)c*NN + m0+m]; }
    __syncthreads();
    int tx = t & 15, ty = t >> 4;
    float hi[4][4], lo[4][4];
    #pragma unroll
    for (int i=0;i<4;i++)
        #pragma unroll
        for (int j=0;j<4;j++){ hi[i][j]=0.f; lo[i][j]=0.f; }
    #pragma unroll 2
    for (int c=0;c<C;c++){
        float av[4], bv[4];
        #pragma unroll
        for (int i=0;i<4;i++) av[i] = As[ty*4+i][c];
        #pragma unroll
        for (int j=0;j<4;j++) bv[j] = Bs[c][tx*4+j];
        #pragma unroll
        for (int i=0;i<4;i++)
            #pragma unroll
            for (int j=0;j<4;j++)
                dfMac(hi[i][j], lo[i][j], av[i], bv[j]);
    }
    #pragma unroll
    for (int i=0;i<4;i++){
        long row = n0 + ty*4 + i;
        #pragma unroll
        for (int j=0;j<4;j++){
            long col = m0 + tx*4 + j;
            Ghi[((long)b*NN + row)*NN + col] = hi[i][j];
            Glo[((long)b*NN + row)*NN + col] = lo[i][j];
        }
    }
}

// ---------------- small helpers ----------------
__global__ void prep_w_k(const float* __restrict__ We1, const float* __restrict__ We2)
{
    int i = blockIdx.x*256 + threadIdx.x;
    if (i < 64*3){ int o=i/3, c=i-o*3;
        g_Wa1[c*64+o] = We1[o*6+c];
        g_Wb1[c*64+o] = We1[o*6+3+c];
    }
    if (i < 64*64){ int o=i>>6, c=i&63;
        g_Wa2[c*64+o] = We2[o*128+c];
        g_Wb2[c*64+o] = We2[o*128+64+c];
    }
}

__global__ void transpose3_k(const float* __restrict__ x)
{
    int b=blockIdx.y; int n=blockIdx.x*256+threadIdx.x;
    #pragma unroll
    for (int c=0;c<3;c++)
        g_xt[((long)b*NN+n)*3+c] = x[(long)b*3*NN + (long)c*NN + n];
}

// xx = sum_c x_c^2, rounded mul then sequential add (bit-matches jnp.sum(x*x) elementwise chain)
__global__ void xx1_k(const float* __restrict__ x)
{
    int b=blockIdx.y; int n=blockIdx.x*256+threadIdx.x;
    float s=0.f;
    #pragma unroll
    for (int c=0;c<3;c++){
        float v = x[(long)b*3*NN+(long)c*NN+n];
        s = __fadd_rn(s, __fmul_rn(v,v));
    }
    g_xx[b*NN+n]=s;
}

__global__ void xx2_k()   // from g_feat channels 0..63 (f1)
{
    int b=blockIdx.y; int n=blockIdx.x*256+threadIdx.x;
    const float* p = g_feat + (long)b*128*NN + n;
    float s=0.f;
    #pragma unroll 8
    for (int c=0;c<64;c++){
        float v = p[(long)c*NN];
        s = __fadd_rn(s, __fmul_rn(v,v));
    }
    g_xx[b*NN+n]=s;
}

// ---------------- top-k on double-float pdist = 2*G - xxn - xxm ----------------
__global__ void __launch_bounds__(256) topk_df_k()
{
    int b = blockIdx.y, n = blockIdx.x, t = threadIdx.x;
    const float* rh = g_big + ((long)b*NN + n)*NN;
    const float* rl = g_glo + ((long)b*NN + n)*NN;
    const float* xxb = g_xx + (long)b*NN;
    float xxn = xxb[n];
    float lh[8], ll[8];
    #pragma unroll
    for (int j=0;j<8;j++){
        int m = t + j*256;
        float hi = 2.f*rh[m], lo = 2.f*rl[m];   // exact scaling
        dfAddF(hi, lo, -xxn);
        dfAddF(hi, lo, -xxb[m]);
        lh[j]=hi; ll[j]=lo;
    }
    __shared__ float s_h[8], s_l[8]; __shared__ int s_i[8]; __shared__ int s_win;
    int* out = g_idx + ((long)b*NN + n)*KK;
    for (int kk=0; kk<KK; kk++){
        float bh = -INFINITY, bl = 0.f; int bi = 1<<30;
        #pragma unroll
        for (int j=0;j<8;j++){
            int m = t + j*256;
            float h = lh[j], l = ll[j];
            if (h > bh || (h == bh && (l > bl || (l == bl && m < bi)))) { bh=h; bl=l; bi=m; }
        }
        #pragma unroll
        for (int off=16; off; off>>=1){
            float oh = __shfl_down_sync(0xffffffffu, bh, off);
            float ol = __shfl_down_sync(0xffffffffu, bl, off);
            int   oi = __shfl_down_sync(0xffffffffu, bi, off);
            if (oh > bh || (oh == bh && (ol > bl || (ol == bl && oi < bi)))) { bh=oh; bl=ol; bi=oi; }
        }
        if ((t&31)==0){ s_h[t>>5]=bh; s_l[t>>5]=bl; s_i[t>>5]=bi; }
        __syncthreads();
        if (t < 32){
            if (t < 8){ bh=s_h[t]; bl=s_l[t]; bi=s_i[t]; } else { bh=-INFINITY; bl=0.f; bi=1<<30; }
            #pragma unroll
            for (int off=4; off; off>>=1){
                float oh = __shfl_down_sync(0xffffffffu, bh, off);
                float ol = __shfl_down_sync(0xffffffffu, bl, off);
                int   oi = __shfl_down_sync(0xffffffffu, bi, off);
                if (oh > bh || (oh == bh && (ol > bl || (ol == bl && oi < bi)))) { bh=oh; bl=ol; bi=oi; }
            }
            if (t==0){ s_win = bi; out[kk] = bi; }
        }
        __syncthreads();
        int w = s_win;
        if ((w & 255) == t) lh[w>>8] = -INFINITY;
    }
}

// ---------------- EdgeConv: compute e, store to g_big, max over k ----------------
template<int C>
__global__ void __launch_bounds__(256) ec_compute_t(
    const float* __restrict__ src,   // [B][NN][C] (n-major)
    const float* __restrict__ Wa,    // [C][64]
    const float* __restrict__ Wb,    // [C][64]
    const float* __restrict__ be)
{
    int b = blockIdx.y, n = blockIdx.x, t = threadIdx.x;
    __shared__ int   sidx[KK];
    __shared__ float cen[C];
    __shared__ float Was[C*64];
    __shared__ float Wbs[C*64];
    __shared__ float dr[KK][C + (C==64 ? 1 : 0)];
    __shared__ float sm[256];

    const float* sb = src + (long)b*NN*C;
    if (t < KK) sidx[t] = g_idx[((long)b*NN+n)*KK + t];
    if (t < C)  cen[t] = sb[(long)n*C + t];
    for (int i=t; i<C*64; i+=256){ Was[i] = Wa[i]; Wbs[i] = Wb[i]; }
    __syncthreads();

    for (int i=t; i<KK*C; i+=256){
        int k = i/C, c = i - k*C;
        dr[k][c] = __fsub_rn(sb[(long)sidx[k]*C + c], cen[c]);
    }
    __syncthreads();

    int o = t & 63, kg = t >> 6;
    float bo = be[o];
    float* eout = g_big + (((long)b*NN + n)*KK)*64;
    float mx = -INFINITY;
    #pragma unroll
    for (int j=0;j<8;j++){
        int k = kg*8 + j;
        float acc = 0.f;
        #pragma unroll
        for (int c=0;c<C;c++) acc = fmaf(Was[c*64+o], dr[k][c], acc);
        #pragma unroll
        for (int c=0;c<C;c++) acc = fmaf(Wbs[c*64+o], cen[c], acc);
        acc = __fadd_rn(acc, bo);
        eout[(long)k*64 + o] = acc;
        mx = fmaxf(mx, acc);
    }
    sm[t]=mx;
    __syncthreads();
    if (t < 128) sm[t]=fmaxf(sm[t],sm[t+128]);
    __syncthreads();
    if (t < 64)  g_m1t[((long)b*NN+n)*64 + t] = fmaxf(sm[t],sm[t+64]);
}

// ---------------- EdgeConv BN stats: deterministic two-pass, fp64 ----------------
#define ECROWS (BB*NN*KK)        // 524288 rows of 64 channels
#define ECBLK  128               // partial blocks

__global__ void __launch_bounds__(256) ec_mean_part_k()
{
    int t = threadIdx.x, o = t & 63, rg = t >> 6;
    long rows_per_block = ECROWS / ECBLK;    // 4096
    long r0 = (long)blockIdx.x * rows_per_block;
    double acc = 0.0;
    for (long i = rg; i < rows_per_block; i += 4)
        acc += (double)g_big[(r0 + i)*64 + o];
    __shared__ double sd[256];
    sd[t] = acc;
    __syncthreads();
    if (t < 64)
        g_part[(long)o*ECBLK + blockIdx.x] = ((sd[t] + sd[t+64]) + sd[t+128]) + sd[t+192];
}

__global__ void ec_mean_fin_k()
{
    int o = threadIdx.x;
    if (o < 64){
        double s = 0.0;
        for (int j=0;j<ECBLK;j++) s += g_part[(long)o*ECBLK + j];
        g_mean[o] = (float)(s / (double)ECROWS);
    }
}

__global__ void __launch_bounds__(256) ec_var_part_k()
{
    int t = threadIdx.x, o = t & 63, rg = t >> 6;
    long rows_per_block = ECROWS / ECBLK;
    long r0 = (long)blockIdx.x * rows_per_block;
    float m = g_mean[o];
    double acc = 0.0;
    for (long i = rg; i < rows_per_block; i += 4){
        float d = __fsub_rn(g_big[(r0 + i)*64 + o], m);
        acc += (double)__fmul_rn(d,d);
    }
    __shared__ double sd[256];
    sd[t] = acc;
    __syncthreads();
    if (t < 64)
        g_part[(long)o*ECBLK + blockIdx.x] = ((sd[t] + sd[t+64]) + sd[t+128]) + sd[t+192];
}

__global__ void ec_var_fin_k()
{
    int o = threadIdx.x;
    if (o < 64){
        double s = 0.0;
        for (int j=0;j<ECBLK;j++) s += g_part[(long)o*ECBLK + j];
        float var = (float)(s / (double)ECROWS);
        g_sden[o] = __fsqrt_rn(__fadd_rn(var, 1e-5f));
    }
}

// normalize max-buffer -> feat slice [b][c][n] (+ optional f1t [b][n][c])
__global__ void __launch_bounds__(256) ec_norm_k(float* __restrict__ featslice,
                                                 float* __restrict__ f1t)
{
    int b = blockIdx.y, t = threadIdx.x;
    int n = blockIdx.x*4 + (t>>6), c = t & 63;
    float v = g_m1t[((long)b*NN+n)*64 + c];
    v = fmaxf(__fdiv_rn(__fsub_rn(v, g_mean[c]), g_sden[c]), 0.f);
    featslice[(long)b*128*NN + (long)c*NN + n] = v;
    if (f1t) f1t[((long)b*NN+n)*64 + c] = v;
}

// ---------------- BN stats over [B][C][N]: deterministic two-pass, fp64 ----------------
__global__ void __launch_bounds__(256) stats_mean_k(const float* __restrict__ z, int C)
{
    int c = blockIdx.x, t = threadIdx.x;
    double s = 0.0;
    for (int i=t; i<BB*NN; i+=256){
        int b = i>>11, n = i&(NN-1);
        s += (double)z[((long)b*C + c)*NN + n];
    }
    __shared__ double sd[256];
    sd[t]=s; __syncthreads();
    for (int off=128; off; off>>=1){
        if (t<off) sd[t]+=sd[t+off];
        __syncthreads();
    }
    if (t==0) g_mean[c] = (float)(sd[0] / (double)(BB*NN));
}

__global__ void __launch_bounds__(256) stats_var_k(const float* __restrict__ z, int C)
{
    int c = blockIdx.x, t = threadIdx.x;
    float m = g_mean[c];
    double s = 0.0;
    for (int i=t; i<BB*NN; i+=256){
        int b = i>>11, n = i&(NN-1);
        float d = __fsub_rn(z[((long)b*C + c)*NN + n], m);
        s += (double)__fmul_rn(d,d);
    }
    __shared__ double sd[256];
    sd[t]=s; __syncthreads();
    for (int off=128; off; off>>=1){
        if (t<off) sd[t]+=sd[t+off];
        __syncthreads();
    }
    if (t==0){
        float var = (float)(sd[0] / (double)(BB*NN));
        g_sden[c] = __fsqrt_rn(__fadd_rn(var, 1e-5f));
    }
}

__global__ void bn_relu_k(const float* __restrict__ z, float* __restrict__ o, int C)
{
    long i = (long)blockIdx.x*256 + threadIdx.x;
    int c = (int)((i>>11) & (C-1));
    float v = z[i];
    o[i] = fmaxf(__fdiv_rn(__fsub_rn(v, g_mean[c]), g_sden[c]), 0.f);
}

__global__ void bn_relu_add_k(const float* __restrict__ u, const float* __restrict__ xin,
                              long xs, float* __restrict__ o)
{
    long i = (long)blockIdx.x*256 + threadIdx.x;
    long b = i/(128L*NN); long r = i - b*128L*NN;
    int c = (int)((r>>11) & 127);
    float v = fmaxf(__fdiv_rn(__fsub_rn(u[i], g_mean[c]), g_sden[c]), 0.f);
    o[b*512L*NN + r] = __fadd_rn(xin[b*xs + r], v);
}

__global__ void diff_k(const float* __restrict__ xin, long xs,
                       const float* __restrict__ xr, float* __restrict__ o)
{
    long i = (long)blockIdx.x*256 + threadIdx.x;
    long b = i/(128L*NN); long r = i - b*128L*NN;
    o[i] = __fsub_rn(xin[b*xs + r], xr[i]);
}

// ---------------- attention softmax / colsum / normalize ----------------
__global__ void __launch_bounds__(256) softmax_rows_k()
{
    int b=blockIdx.y, n=blockIdx.x, t=threadIdx.x;
    float* row = g_big + ((long)b*NN+n)*NN;
    float lv[8]; float mx=-INFINITY;
    #pragma unroll
    for (int j=0;j<8;j++){ lv[j]=row[t+j*256]; mx=fmaxf(mx,lv[j]); }
    __shared__ float sw[8]; __shared__ float sbc;
    #pragma unroll
    for (int off=16;off;off>>=1) mx=fmaxf(mx,__shfl_xor_sync(0xffffffffu,mx,off));
    if ((t&31)==0) sw[t>>5]=mx;
    __syncthreads();
    if (t==0){ float m=sw[0]; for(int i=1;i<8;i++) m=fmaxf(m,sw[i]); sbc=m; }
    __syncthreads();
    mx = sbc;
    float s=0.f;
    #pragma unroll
    for (int j=0;j<8;j++){ lv[j]=expf(__fsub_rn(lv[j],mx)); s=__fadd_rn(s,lv[j]); }
    #pragma unroll
    for (int off=16;off;off>>=1) s=__fadd_rn(s,__shfl_xor_sync(0xffffffffu,s,off));
    __syncthreads();
    if ((t&31)==0) sw[t>>5]=s;
    __syncthreads();
    if (t==0){ float m=0.f; for(int i=0;i<8;i++) m=__fadd_rn(m,sw[i]); sbc=m; }
    __syncthreads();
    float den = sbc;
    #pragma unroll
    for (int j=0;j<8;j++) row[t+j*256]=__fdiv_rn(lv[j],den);
}

__global__ void colsum_k()
{
    int b=blockIdx.y; int m=blockIdx.x*256+threadIdx.x;
    const float* p = g_big + (long)b*NN*NN + m;
    float s=0.f;
    #pragma unroll 8
    for (int nr=0; nr<NN; nr++) s = __fadd_rn(s, p[(long)nr*NN]);
    g_cs[b*NN+m]=s;
}

// attn[n][m] /= (1e-6 + cs[m])
__global__ void attn_div_k()
{
    long i = (long)blockIdx.x*256 + threadIdx.x;
    int m = (int)(i & (NN-1));
    int b = (int)(i >> 22);            // NN*NN = 2^22
    float d = __fadd_rn(1e-6f, g_cs[b*NN+m]);
    g_big[i] = __fdiv_rn(g_big[i], d);
}

// ---------------- head ----------------
__global__ void gmax_k()
{
    int o=blockIdx.x, b=blockIdx.y, t=threadIdx.x;
    const float* p = g_fuse + ((long)b*1024 + o)*NN;
    float m=-INFINITY;
    for (int i=t;i<NN;i+=256) m=fmaxf(m,p[i]);
    __shared__ float sm[256]; sm[t]=m; __syncthreads();
    for (int off=128;off;off>>=1){ if(t<off) sm[t]=fmaxf(sm[t],sm[t+off]); __syncthreads(); }
    if (t==0) g_gm[b*1024+o]=sm[0];
}

__global__ void c0_k(const float* __restrict__ Wc1, const float* __restrict__ bc1)
{
    int o=blockIdx.x, b=blockIdx.y, t=threadIdx.x;
    float s=0.f;
    for (int c=t; c<1024; c+=256)
        s = fmaf(Wc1[(long)o*1536 + c], g_gm[b*1024+c], s);
    __shared__ float ss[256]; ss[t]=s; __syncthreads();
    for (int off=128;off;off>>=1){ if(t<off) ss[t]=__fadd_rn(ss[t],ss[t+off]); __syncthreads(); }
    if (t==0) g_c0[b*512+o]=__fadd_rn(ss[0],bc1[o]);
}

// ---------------- host ----------------
template<typename T, size_t NSZ>
static T* SP(T (&arr)[NSZ]){ void* p=nullptr; cudaGetSymbolAddress(&p, arr); return (T*)p; }

static void sgemm(const float* A,int lda,long sA,const float* B,int ldb,long sB,
                  float* C,int ldc,long sC,int M,int Nn,int Kd,
                  const float* bias,const float* rowbias,int transOut)
{
    dim3 g((Nn+TBN-1)/TBN,(M+TBM-1)/TBM,BB);
    sgemm_k<<<g,256>>>(A,lda,sA,B,ldb,sB,C,ldc,sC,M,Nn,Kd,bias,rowbias,transOut);
}

extern "C" void kernel_launch(void* const* d_in, const int* in_sizes, int n_in,
                              void* d_out, int out_size)
{
    const float* x   = (const float*)d_in[0];
    const float* We1 = (const float*)d_in[1];
    const float* be1 = (const float*)d_in[2];
    const float* We2 = (const float*)d_in[3];
    const float* be2 = (const float*)d_in[4];
    const float* Wq  = (const float*)d_in[5];
    const float* Wk  = (const float*)d_in[6];
    const float* Wt  = (const float*)d_in[7];
    const float* bt  = (const float*)d_in[8];
    const float* Wf  = (const float*)d_in[9];
    const float* bf  = (const float*)d_in[10];
    const float* Wc1 = (const float*)d_in[11];
    const float* bc1 = (const float*)d_in[12];
    const float* Wc2 = (const float*)d_in[13];
    const float* bc2 = (const float*)d_in[14];
    const float* Wc3 = (const float*)d_in[15];
    const float* bc3 = (const float*)d_in[16];
    float* out = (float*)d_out;

    float* big  = SP(g_big);
    float* glo  = SP(g_glo);
    float* xt   = SP(g_xt);
    float* f1t  = SP(g_f1t);
    float* feat = SP(g_feat);
    float* cat  = SP(g_cat);
    float* xqt  = SP(g_xqt);
    float* xk   = SP(g_xk);
    float* xr   = SP(g_xr);
    float* tb   = SP(g_tb);
    float* ub   = SP(g_ub);
    float* fuse = SP(g_fuse);
    float* c0   = SP(g_c0);
    float* h1   = SP(g_h1);
    float* h2   = SP(g_h2);
    float* Wa1  = SP(g_Wa1); float* Wb1 = SP(g_Wb1);
    float* Wa2  = SP(g_Wa2); float* Wb2 = SP(g_Wb2);

    // ---- weight prep ----
    prep_w_k<<<16,256>>>(We1, We2);

    // ---- EdgeConv block 1 (C=3) ----
    xx1_k<<<dim3(NN/256,BB),256>>>(x);
    transpose3_k<<<dim3(NN/256,BB),256>>>(x);
    gram_df_t<3><<<dim3(NN/64,NN/64,BB),256>>>(xt, (long)NN*3, x, 3L*NN, big, glo);   // G1 (df)
    topk_df_k<<<dim3(NN,BB),256>>>();
    ec_compute_t<3><<<dim3(NN,BB),256>>>(xt, Wa1, Wb1, be1);                          // e -> g_big
    ec_mean_part_k<<<ECBLK,256>>>();  ec_mean_fin_k<<<1,64>>>();
    ec_var_part_k<<<ECBLK,256>>>();   ec_var_fin_k<<<1,64>>>();
    ec_norm_k<<<dim3(NN/4,BB),256>>>(feat, f1t);                                      // f1 + f1t
    xx2_k<<<dim3(NN/256,BB),256>>>();

    // ---- EdgeConv block 2 (C=64) ----
    gram_df_t<64><<<dim3(NN/64,NN/64,BB),256>>>(f1t, (long)NN*64, feat, 128L*NN, big, glo); // G2 (df)
    topk_df_k<<<dim3(NN,BB),256>>>();
    ec_compute_t<64><<<dim3(NN,BB),256>>>(f1t, Wa2, Wb2, be2);                        // e -> g_big
    ec_mean_part_k<<<ECBLK,256>>>();  ec_mean_fin_k<<<1,64>>>();
    ec_var_part_k<<<ECBLK,256>>>();   ec_var_fin_k<<<1,64>>>();
    ec_norm_k<<<dim3(NN/4,BB),256>>>(feat + 64L*NN, (float*)0);                       // f2

    // ---- 4 SA layers ----
    for (int il=0; il<4; il++){
        const float* xin = (il==0)? feat : cat + (long)(il-1)*128*NN;
        long xs = (il==0)? 128L*NN : 512L*NN;
        sgemm(Wq+il*32*128,128,0, xin,NN,xs, xqt,32,32L*NN, 32,NN,128, 0,0,1);   // xq^T
        sgemm(Wk+il*32*128,128,0, xin,NN,xs, xk, NN,32L*NN, 32,NN,128, 0,0,0);   // xk
        sgemm(xqt,32,32L*NN, xk,NN,32L*NN, big,NN,(long)NN*NN, NN,NN,32, 0,0,0); // energy
        softmax_rows_k<<<dim3(NN,BB),256>>>();
        colsum_k<<<dim3(NN/256,BB),256>>>();
        attn_div_k<<<(int)(((long)BB*NN*NN)/256),256>>>();
        sgemm(xin,NN,xs, big,NN,(long)NN*NN, xr,NN,128L*NN, 128,NN,NN, 0,0,0);   // x@attn_norm
        diff_k<<<(BB*128*NN)/256,256>>>(xin, xs, xr, tb);                        // t = x - xr
        sgemm(Wt+il*128*128,128,0, tb,NN,128L*NN, ub,NN,128L*NN, 128,NN,128, bt+il*128,0,0);
        stats_mean_k<<<128,256>>>(ub,128);
        stats_var_k<<<128,256>>>(ub,128);
        bn_relu_add_k<<<(BB*128*NN)/256,256>>>(ub, xin, xs, cat + (long)il*128*NN);
    }

    // ---- head ----
    sgemm(Wf,512,0, cat,NN,512L*NN, fuse,NN,1024L*NN, 1024,NN,512, bf,0,0);
    stats_mean_k<<<1024,256>>>(fuse,1024);
    stats_var_k<<<1024,256>>>(fuse,1024);
    bn_relu_k<<<(BB*1024*NN)/256,256>>>(fuse,fuse,1024);
    gmax_k<<<dim3(1024,BB),256>>>();
    c0_k<<<dim3(512,BB),256>>>(Wc1, bc1);
    sgemm(Wc1+1024,1536,0, cat,NN,512L*NN, h1,NN,512L*NN, 512,NN,512, 0,c0,0);
    stats_mean_k<<<512,256>>>(h1,512);
    stats_var_k<<<512,256>>>(h1,512);
    bn_relu_k<<<(BB*512*NN)/256,256>>>(h1,h1,512);
    sgemm(Wc2,512,0, h1,NN,512L*NN, h2,NN,256L*NN, 256,NN,512, bc2,0,0);
    stats_mean_k<<<256,256>>>(h2,256);
    stats_var_k<<<256,256>>>(h2,256);
    bn_relu_k<<<(BB*256*NN)/256,256>>>(h2,h2,256);
    sgemm(Wc3,256,0, h2,NN,256L*NN, out,NN,13L*NN, 13,NN,256, bc3,0,0);
}

// round 8
// speedup vs baseline: 1.1774x; 1.1774x over previous
#include <cuda_runtime.h>
#include <math.h>

#define BB 8
#define NN 2048
#define KK 32

// ---------------- scratch (device globals; no allocations) ----------------
__device__ float  g_big[BB*NN*NN];     // 134MB: G_hi (knn) / energy / attn
__device__ float  g_glo[BB*NN*NN];     // 134MB: G_lo (df tail for knn)
__device__ int    g_idx[BB*NN*KK];
__device__ float  g_xt [BB*NN*3];
__device__ float  g_xx [BB*NN];
__device__ float  g_Wa1[3*64],  g_Wb1[3*64];    // transposed [c][o]
__device__ float  g_Wa2[64*64], g_Wb2[64*64];
__device__ float  g_m1t[BB*NN*64];
__device__ float  g_f1t[BB*NN*64];
__device__ float  g_feat[BB*128*NN];
__device__ float  g_cat [BB*512*NN];
__device__ float  g_xqt [BB*NN*32];
__device__ float  g_xk  [BB*32*NN];
__device__ float  g_cs  [BB*NN];
__device__ float  g_xr  [BB*128*NN];
__device__ float  g_tb  [BB*128*NN];
__device__ float  g_ub  [BB*128*NN];
__device__ float  g_fuse[BB*1024*NN];
__device__ float  g_gm  [BB*1024];
__device__ float  g_c0  [BB*512];
__device__ float  g_h1  [BB*512*NN];
__device__ float  g_h2  [BB*256*NN];
__device__ float  g_sum[64];
__device__ float  g_sumsq[64];
__device__ float  g_mean[1024];
__device__ float  g_rstd[1024];

// ---------------- double-float helpers ----------------
__device__ __forceinline__ void twoSum(float a, float b, float& s, float& e){
    s = __fadd_rn(a,b);
    float bb = __fsub_rn(s,a);
    e = __fadd_rn(__fsub_rn(a, __fsub_rn(s,bb)), __fsub_rn(b,bb));
}
__device__ __forceinline__ void dfMac(float& hi, float& lo, float a, float b){
    float p = __fmul_rn(a,b);
    float e = fmaf(a,b,-p);
    float s, err;
    twoSum(hi, p, s, err);
    lo = __fadd_rn(lo, __fadd_rn(err, e));
    float hi2 = __fadd_rn(s, lo);
    lo = __fsub_rn(lo, __fsub_rn(hi2, s));
    hi = hi2;
}
__device__ __forceinline__ void dfAddF(float& hi, float& lo, float f){
    float s, e;
    twoSum(hi, f, s, e);
    lo = __fadd_rn(lo, e);
    float hi2 = __fadd_rn(s, lo);
    lo = __fsub_rn(lo, __fsub_rn(hi2, s));
    hi = hi2;
}

// ---------------- FMA-pipe exp (no MUFU), ~2ulp, x <= 0 ----------------
__device__ __forceinline__ float fast_exp(float x){
    float z  = fmaf(x, 1.442695041f, 12582912.0f);          // magic round
    float nf = __fsub_rn(z, 12582912.0f);
    int   ni = (__float_as_int(z) & 0x7FFFFF) - 4194304;
    float r  = fmaf(nf, -0.693145751953125f, x);
    r = fmaf(nf, -1.42860677e-6f, r);
    float p = 1.9875691500e-4f;
    p = fmaf(p, r, 1.3981999507e-3f);
    p = fmaf(p, r, 8.3334519073e-3f);
    p = fmaf(p, r, 4.1665795894e-2f);
    p = fmaf(p, r, 1.6666665459e-1f);
    p = fmaf(p, r, 5.0000001201e-1f);
    float e = __fadd_rn(fmaf(__fmul_rn(r,r), p, r), 1.0f);
    if (ni < -126) ni = -126;
    float sc = __int_as_float((ni + 127) << 23);
    return __fmul_rn(e, sc);
}

// ---------------- generic tiled SGEMM (honest fp32) ----------------
#define TBM 128
#define TBN 128
#define TBK 16

__global__ void __launch_bounds__(256) sgemm_k(
    const float* __restrict__ A, int lda, long sA,
    const float* __restrict__ Bm, int ldb, long sB,
    float* __restrict__ C, int ldc, long sC,
    int M, int Nn, int Kd,
    const float* __restrict__ bias,
    const float* __restrict__ rowbias,
    const float* __restrict__ colscale,  // per-batch [Nn]: v /= (1e-6+cs)
    int transOut)
{
    __shared__ float As[TBK][TBM+4];
    __shared__ float Bs[TBK][TBN+4];
    int b = blockIdx.z;
    const float* Ab = A + (long)b*sA;
    const float* Bb = Bm + (long)b*sB;
    float* Cb = C + (long)b*sC;
    int m0 = blockIdx.y*TBM, n0 = blockIdx.x*TBN;
    int tid = threadIdx.x;
    int tx = tid & 15, ty = tid >> 4;

    float acc[8][8];
    #pragma unroll
    for (int i=0;i<8;i++)
        #pragma unroll
        for (int j=0;j<8;j++) acc[i][j]=0.f;

    int aRow = tid >> 1;
    int aCol0 = (tid & 1) * 8;
    int bRow = tid >> 4;
    int bCol0 = (tid & 15) * 8;

    for (int k0 = 0; k0 < Kd; k0 += TBK) {
        #pragma unroll
        for (int j = 0; j < 8; j++) {
            int m = aRow, k = aCol0 + j;
            float v = 0.f;
            if (m0+m < M && k0+k < Kd) v = Ab[(long)(m0+m)*lda + k0+k];
            As[k][m] = v;
        }
        #pragma unroll
        for (int j = 0; j < 8; j++) {
            int k = bRow, n = bCol0 + j;
            float v = 0.f;
            if (k0+k < Kd && n0+n < Nn) v = Bb[(long)(k0+k)*ldb + n0+n];
            Bs[k][n] = v;
        }
        __syncthreads();
        #pragma unroll
        for (int kk = 0; kk < TBK; kk++) {
            float4 a0 = *reinterpret_cast<const float4*>(&As[kk][ty*8]);
            float4 a1 = *reinterpret_cast<const float4*>(&As[kk][ty*8+4]);
            float4 b0 = *reinterpret_cast<const float4*>(&Bs[kk][tx*8]);
            float4 b1 = *reinterpret_cast<const float4*>(&Bs[kk][tx*8+4]);
            float ra[8] = {a0.x,a0.y,a0.z,a0.w,a1.x,a1.y,a1.z,a1.w};
            float rb[8] = {b0.x,b0.y,b0.z,b0.w,b1.x,b1.y,b1.z,b1.w};
            #pragma unroll
            for (int i=0;i<8;i++)
                #pragma unroll
                for (int j=0;j<8;j++)
                    acc[i][j] = fmaf(ra[i], rb[j], acc[i][j]);
        }
        __syncthreads();
    }
    #pragma unroll
    for (int i=0;i<8;i++){
        int row = m0 + ty*8 + i;
        if (row >= M) continue;
        float rb0 = 0.f;
        bool hasb = false;
        if (bias){    rb0 = __fadd_rn(rb0, bias[row]); hasb = true; }
        if (rowbias){ rb0 = __fadd_rn(rb0, rowbias[(long)b*M + row]); hasb = true; }
        #pragma unroll
        for (int j=0;j<8;j++){
            int col = n0 + tx*8 + j;
            if (col >= Nn) continue;
            float v = acc[i][j];
            if (hasb) v = __fadd_rn(v, rb0);
            if (colscale) v = __fdiv_rn(v, __fadd_rn(1e-6f, colscale[(long)b*Nn + col]));
            if (!transOut) Cb[(long)row*ldc + col] = v;
            else           Cb[(long)col*ldc + row] = v;   // ldc == M
        }
    }
}

// ---------------- double-float Gram (C==64 path exploits symmetry) ----------------
template<int C>
__global__ void __launch_bounds__(256) gram_df_t(
    const float* __restrict__ At, long sA,   // [B][NN][C]  n-major
    const float* __restrict__ Bc, long sB,   // [B][>=C][NN] c-major, ldb=NN
    float* __restrict__ Ghi, float* __restrict__ Glo)
{
    __shared__ float As[64][(C==3)?3:65];
    __shared__ float Bs[C][65];
    int b = blockIdx.z;
    int bi = blockIdx.y, bj = blockIdx.x;
    if (C == 64 && bj < bi) return;           // symmetric: upper triangle only
    int n0 = bi*64, m0 = bj*64;
    int t = threadIdx.x;
    const float* Ab = At + (long)b*sA;
    const float* Bb = Bc + (long)b*sB;
    for (int i=t; i<64*C; i+=256){ int n=i/C, c=i-n*C; As[n][c] = Ab[(long)(n0+n)*C + c]; }
    for (int i=t; i<C*64; i+=256){ int c=i>>6, m=i&63;  Bs[c][m] = Bb[(long)c*NN + m0+m]; }
    __syncthreads();
    int tx = t & 15, ty = t >> 4;
    float hi[4][4], lo[4][4];
    #pragma unroll
    for (int i=0;i<4;i++)
        #pragma unroll
        for (int j=0;j<4;j++){ hi[i][j]=0.f; lo[i][j]=0.f; }
    #pragma unroll 2
    for (int c=0;c<C;c++){
        float av[4], bv[4];
        #pragma unroll
        for (int i=0;i<4;i++) av[i] = As[ty*4+i][c];
        #pragma unroll
        for (int j=0;j<4;j++) bv[j] = Bs[c][tx*4+j];
        #pragma unroll
        for (int i=0;i<4;i++)
            #pragma unroll
            for (int j=0;j<4;j++)
                dfMac(hi[i][j], lo[i][j], av[i], bv[j]);
    }
    #pragma unroll
    for (int i=0;i<4;i++){
        long row = n0 + ty*4 + i;
        #pragma unroll
        for (int j=0;j<4;j++){
            long col = m0 + tx*4 + j;
            Ghi[((long)b*NN + row)*NN + col] = hi[i][j];
            Glo[((long)b*NN + row)*NN + col] = lo[i][j];
        }
    }
    if (C == 64 && bj > bi){
        // mirror tile: stage transposed in smem, write coalesced
        __syncthreads();
        #pragma unroll
        for (int i=0;i<4;i++)
            #pragma unroll
            for (int j=0;j<4;j++){
                As[tx*4+j][ty*4+i] = hi[i][j];
                Bs[tx*4+j][ty*4+i] = lo[i][j];
            }
        __syncthreads();
        for (int e2=t; e2<64*64; e2+=256){
            int r = e2 >> 6, cix = e2 & 63;
            Ghi[((long)b*NN + m0 + r)*NN + n0 + cix] = As[r][cix];
            Glo[((long)b*NN + m0 + r)*NN + n0 + cix] = Bs[r][cix];
        }
    }
}

// ---------------- small helpers ----------------
__global__ void prep_w_k(const float* __restrict__ We1, const float* __restrict__ We2)
{
    int i = blockIdx.x*256 + threadIdx.x;
    if (i < 64*3){ int o=i/3, c=i-o*3;
        g_Wa1[c*64+o] = We1[o*6+c];
        g_Wb1[c*64+o] = We1[o*6+3+c];
    }
    if (i < 64*64){ int o=i>>6, c=i&63;
        g_Wa2[c*64+o] = We2[o*128+c];
        g_Wb2[c*64+o] = We2[o*128+64+c];
    }
}

__global__ void transpose3_k(const float* __restrict__ x)
{
    int b=blockIdx.y; int n=blockIdx.x*256+threadIdx.x;
    #pragma unroll
    for (int c=0;c<3;c++)
        g_xt[((long)b*NN+n)*3+c] = x[(long)b*3*NN + (long)c*NN + n];
}

__global__ void xx1_k(const float* __restrict__ x)
{
    int b=blockIdx.y; int n=blockIdx.x*256+threadIdx.x;
    float s=0.f;
    #pragma unroll
    for (int c=0;c<3;c++){
        float v = x[(long)b*3*NN+(long)c*NN+n];
        s = __fadd_rn(s, __fmul_rn(v,v));
    }
    g_xx[b*NN+n]=s;
}

__global__ void xx2_k()   // from g_feat channels 0..63 (f1)
{
    int b=blockIdx.y; int n=blockIdx.x*256+threadIdx.x;
    const float* p = g_feat + (long)b*128*NN + n;
    float s=0.f;
    #pragma unroll 8
    for (int c=0;c<64;c++){
        float v = p[(long)c*NN];
        s = __fadd_rn(s, __fmul_rn(v,v));
    }
    g_xx[b*NN+n]=s;
}

// ---------------- top-k on double-float pdist ----------------
__global__ void __launch_bounds__(256) topk_df_k()
{
    int b = blockIdx.y, n = blockIdx.x, t = threadIdx.x;
    const float* rh = g_big + ((long)b*NN + n)*NN;
    const float* rl = g_glo + ((long)b*NN + n)*NN;
    const float* xxb = g_xx + (long)b*NN;
    float xxn = xxb[n];
    float lh[8], ll[8];
    #pragma unroll
    for (int j=0;j<8;j++){
        int m = t + j*256;
        float hi = 2.f*rh[m], lo = 2.f*rl[m];
        dfAddF(hi, lo, -xxn);
        dfAddF(hi, lo, -xxb[m]);
        lh[j]=hi; ll[j]=lo;
    }
    __shared__ float s_h[8], s_l[8]; __shared__ int s_i[8]; __shared__ int s_win;
    int* out = g_idx + ((long)b*NN + n)*KK;
    for (int kk=0; kk<KK; kk++){
        float bh = -INFINITY, bl = 0.f; int bi = 1<<30;
        #pragma unroll
        for (int j=0;j<8;j++){
            int m = t + j*256;
            float h = lh[j], l = ll[j];
            if (h > bh || (h == bh && (l > bl || (l == bl && m < bi)))) { bh=h; bl=l; bi=m; }
        }
        #pragma unroll
        for (int off=16; off; off>>=1){
            float oh = __shfl_down_sync(0xffffffffu, bh, off);
            float ol = __shfl_down_sync(0xffffffffu, bl, off);
            int   oi = __shfl_down_sync(0xffffffffu, bi, off);
            if (oh > bh || (oh == bh && (ol > bl || (ol == bl && oi < bi)))) { bh=oh; bl=ol; bi=oi; }
        }
        if ((t&31)==0){ s_h[t>>5]=bh; s_l[t>>5]=bl; s_i[t>>5]=bi; }
        __syncthreads();
        if (t < 32){
            if (t < 8){ bh=s_h[t]; bl=s_l[t]; bi=s_i[t]; } else { bh=-INFINITY; bl=0.f; bi=1<<30; }
            #pragma unroll
            for (int off=4; off; off>>=1){
                float oh = __shfl_down_sync(0xffffffffu, bh, off);
                float ol = __shfl_down_sync(0xffffffffu, bl, off);
                int   oi = __shfl_down_sync(0xffffffffu, bi, off);
                if (oh > bh || (oh == bh && (ol > bl || (ol == bl && oi < bi)))) { bh=oh; bl=ol; bi=oi; }
            }
            if (t==0){ s_win = bi; out[kk] = bi; }
        }
        __syncthreads();
        int w = s_win;
        if ((w & 255) == t) lh[w>>8] = -INFINITY;
    }
}

// ---------------- EdgeConv: fused e + max-over-k + one-pass stats ----------------
template<int C>
__global__ void __launch_bounds__(256) ec_pass_t(
    const float* __restrict__ src,   // [B][NN][C] (n-major)
    const float* __restrict__ Wa,    // [C][64]
    const float* __restrict__ Wb,    // [C][64]
    const float* __restrict__ be)
{
    int b = blockIdx.y, n = blockIdx.x, t = threadIdx.x;
    __shared__ int   sidx[KK];
    __shared__ float cen[C];
    __shared__ float Was[C*64];
    __shared__ float Wbs[C*64];
    __shared__ float dr[KK][C + (C==64 ? 1 : 0)];
    __shared__ float sm[256], ss[256], ss2[256];

    const float* sb = src + (long)b*NN*C;
    if (t < KK) sidx[t] = g_idx[((long)b*NN+n)*KK + t];
    if (t < C)  cen[t] = sb[(long)n*C + t];
    for (int i=t; i<C*64; i+=256){ Was[i] = Wa[i]; Wbs[i] = Wb[i]; }
    __syncthreads();

    for (int i=t; i<KK*C; i+=256){
        int k = i/C, c = i - k*C;
        dr[k][c] = __fsub_rn(sb[(long)sidx[k]*C + c], cen[c]);
    }
    __syncthreads();

    int o = t & 63, kg = t >> 6;
    float bo = be[o];
    float mx = -INFINITY, s = 0.f, s2 = 0.f;
    #pragma unroll
    for (int j=0;j<8;j++){
        int k = kg*8 + j;
        float acc = 0.f;
        #pragma unroll
        for (int c=0;c<C;c++) acc = fmaf(Was[c*64+o], dr[k][c], acc);
        #pragma unroll
        for (int c=0;c<C;c++) acc = fmaf(Wbs[c*64+o], cen[c], acc);
        acc = __fadd_rn(acc, bo);
        mx = fmaxf(mx, acc);
        s += acc;
        s2 = fmaf(acc, acc, s2);
    }
    sm[t]=mx; ss[t]=s; ss2[t]=s2;
    __syncthreads();
    if (t < 128){ sm[t]=fmaxf(sm[t],sm[t+128]); ss[t]+=ss[t+128]; ss2[t]+=ss2[t+128]; }
    __syncthreads();
    if (t < 64){
        mx = fmaxf(sm[t],sm[t+64]); s = ss[t]+ss[t+64]; s2 = ss2[t]+ss2[t+64];
        g_m1t[((long)b*NN+n)*64 + t] = mx;
        atomicAdd(&g_sum[t], s);
        atomicAdd(&g_sumsq[t], s2);
    }
}

__global__ void zero_stats_k(){ int t=threadIdx.x; if (t<64){ g_sum[t]=0.f; g_sumsq[t]=0.f; } }

__global__ void ec_fin_k()
{
    int t=threadIdx.x;
    if (t<64){
        float cnt = (float)((long)BB*NN*KK);
        float m = g_sum[t]/cnt;
        float var = fmaxf(g_sumsq[t]/cnt - m*m, 0.f);
        g_mean[t]=m;
        g_rstd[t]=__fdiv_rn(1.f, __fsqrt_rn(__fadd_rn(var, 1e-5f)));
    }
}

// normalize max-buffer -> feat slice [b][c][n] (+ optional f1t [b][n][c])
__global__ void __launch_bounds__(256) ec_norm_k(float* __restrict__ featslice,
                                                 float* __restrict__ f1t)
{
    int b = blockIdx.y, t = threadIdx.x;
    int n = blockIdx.x*4 + (t>>6), c = t & 63;
    float v = g_m1t[((long)b*NN+n)*64 + c];
    v = fmaxf(__fmul_rn(__fsub_rn(v, g_mean[c]), g_rstd[c]), 0.f);
    featslice[(long)b*128*NN + (long)c*NN + n] = v;
    if (f1t) f1t[((long)b*NN+n)*64 + c] = v;
}

// ---------------- BN stats over [B][C][N]: deterministic two-pass, fp64 ----------------
__global__ void __launch_bounds__(256) stats_mean_k(const float* __restrict__ z, int C)
{
    int c = blockIdx.x, t = threadIdx.x;
    double s = 0.0;
    for (int i=t; i<BB*NN; i+=256){
        int b = i>>11, n = i&(NN-1);
        s += (double)z[((long)b*C + c)*NN + n];
    }
    __shared__ double sd[256];
    sd[t]=s; __syncthreads();
    for (int off=128; off; off>>=1){
        if (t<off) sd[t]+=sd[t+off];
        __syncthreads();
    }
    if (t==0) g_mean[c] = (float)(sd[0] / (double)(BB*NN));
}

__global__ void __launch_bounds__(256) stats_var_k(const float* __restrict__ z, int C)
{
    int c = blockIdx.x, t = threadIdx.x;
    float m = g_mean[c];
    double s = 0.0;
    for (int i=t; i<BB*NN; i+=256){
        int b = i>>11, n = i&(NN-1);
        float d = __fsub_rn(z[((long)b*C + c)*NN + n], m);
        s += (double)__fmul_rn(d,d);
    }
    __shared__ double sd[256];
    sd[t]=s; __syncthreads();
    for (int off=128; off; off>>=1){
        if (t<off) sd[t]+=sd[t+off];
        __syncthreads();
    }
    if (t==0){
        float var = (float)(sd[0] / (double)(BB*NN));
        g_rstd[c] = __fdiv_rn(1.f, __fsqrt_rn(__fadd_rn(var, 1e-5f)));
    }
}

__global__ void bn_relu_k(const float* __restrict__ z, float* __restrict__ o, int C)
{
    long i = (long)blockIdx.x*256 + threadIdx.x;
    int c = (int)((i>>11) & (C-1));
    float v = z[i];
    o[i] = fmaxf(__fmul_rn(__fsub_rn(v, g_mean[c]), g_rstd[c]), 0.f);
}

__global__ void bn_relu_add_k(const float* __restrict__ u, const float* __restrict__ xin,
                              long xs, float* __restrict__ o)
{
    long i = (long)blockIdx.x*256 + threadIdx.x;
    long b = i/(128L*NN); long r = i - b*128L*NN;
    int c = (int)((r>>11) & 127);
    float v = fmaxf(__fmul_rn(__fsub_rn(u[i], g_mean[c]), g_rstd[c]), 0.f);
    o[b*512L*NN + r] = __fadd_rn(xin[b*xs + r], v);
}

__global__ void diff_k(const float* __restrict__ xin, long xs,
                       const float* __restrict__ xr, float* __restrict__ o)
{
    long i = (long)blockIdx.x*256 + threadIdx.x;
    long b = i/(128L*NN); long r = i - b*128L*NN;
    o[i] = __fsub_rn(xin[b*xs + r], xr[i]);
}

// ---------------- attention softmax / colsum ----------------
__global__ void __launch_bounds__(256) softmax_rows_k()
{
    int b=blockIdx.y, n=blockIdx.x, t=threadIdx.x;
    float* row = g_big + ((long)b*NN+n)*NN;
    float lv[8]; float mx=-INFINITY;
    #pragma unroll
    for (int j=0;j<8;j++){ lv[j]=row[t+j*256]; mx=fmaxf(mx,lv[j]); }
    __shared__ float sw[8]; __shared__ float sbc;
    #pragma unroll
    for (int off=16;off;off>>=1) mx=fmaxf(mx,__shfl_xor_sync(0xffffffffu,mx,off));
    if ((t&31)==0) sw[t>>5]=mx;
    __syncthreads();
    if (t==0){ float m=sw[0]; for(int i=1;i<8;i++) m=fmaxf(m,sw[i]); sbc=m; }
    __syncthreads();
    mx = sbc;
    float s=0.f;
    #pragma unroll
    for (int j=0;j<8;j++){ lv[j]=fast_exp(__fsub_rn(lv[j],mx)); s=__fadd_rn(s,lv[j]); }
    #pragma unroll
    for (int off=16;off;off>>=1) s=__fadd_rn(s,__shfl_xor_sync(0xffffffffu,s,off));
    __syncthreads();
    if ((t&31)==0) sw[t>>5]=s;
    __syncthreads();
    if (t==0){ float m=0.f; for(int i=0;i<8;i++) m=__fadd_rn(m,sw[i]); sbc=m; }
    __syncthreads();
    float inv = __fdiv_rn(1.f, sbc);
    #pragma unroll
    for (int j=0;j<8;j++) row[t+j*256]=__fmul_rn(lv[j],inv);
}

__global__ void colsum_k()
{
    int b=blockIdx.y; int m=blockIdx.x*256+threadIdx.x;
    const float* p = g_big + (long)b*NN*NN + m;
    float s=0.f;
    #pragma unroll 8
    for (int nr=0; nr<NN; nr++) s = __fadd_rn(s, p[(long)nr*NN]);
    g_cs[b*NN+m]=s;
}

// ---------------- head ----------------
__global__ void gmax_k()
{
    int o=blockIdx.x, b=blockIdx.y, t=threadIdx.x;
    const float* p = g_fuse + ((long)b*1024 + o)*NN;
    float m=-INFINITY;
    for (int i=t;i<NN;i+=256) m=fmaxf(m,p[i]);
    __shared__ float sm[256]; sm[t]=m; __syncthreads();
    for (int off=128;off;off>>=1){ if(t<off) sm[t]=fmaxf(sm[t],sm[t+off]); __syncthreads(); }
    if (t==0) g_gm[b*1024+o]=sm[0];
}

__global__ void c0_k(const float* __restrict__ Wc1, const float* __restrict__ bc1)
{
    int o=blockIdx.x, b=blockIdx.y, t=threadIdx.x;
    float s=0.f;
    for (int c=t; c<1024; c+=256)
        s = fmaf(Wc1[(long)o*1536 + c], g_gm[b*1024+c], s);
    __shared__ float ss[256]; ss[t]=s; __syncthreads();
    for (int off=128;off;off>>=1){ if(t<off) ss[t]=__fadd_rn(ss[t],ss[t+off]); __syncthreads(); }
    if (t==0) g_c0[b*512+o]=__fadd_rn(ss[0],bc1[o]);
}

// ---------------- host ----------------
template<typename T, size_t NSZ>
static T* SP(T (&arr)[NSZ]){ void* p=nullptr; cudaGetSymbolAddress(&p, arr); return (T*)p; }

static void sgemm(const float* A,int lda,long sA,const float* B,int ldb,long sB,
                  float* C,int ldc,long sC,int M,int Nn,int Kd,
                  const float* bias,const float* rowbias,const float* colscale,int transOut)
{
    dim3 g((Nn+TBN-1)/TBN,(M+TBM-1)/TBM,BB);
    sgemm_k<<<g,256>>>(A,lda,sA,B,ldb,sB,C,ldc,sC,M,Nn,Kd,bias,rowbias,colscale,transOut);
}

extern "C" void kernel_launch(void* const* d_in, const int* in_sizes, int n_in,
                              void* d_out, int out_size)
{
    const float* x   = (const float*)d_in[0];
    const float* We1 = (const float*)d_in[1];
    const float* be1 = (const float*)d_in[2];
    const float* We2 = (const float*)d_in[3];
    const float* be2 = (const float*)d_in[4];
    const float* Wq  = (const float*)d_in[5];
    const float* Wk  = (const float*)d_in[6];
    const float* Wt  = (const float*)d_in[7];
    const float* bt  = (const float*)d_in[8];
    const float* Wf  = (const float*)d_in[9];
    const float* bf  = (const float*)d_in[10];
    const float* Wc1 = (const float*)d_in[11];
    const float* bc1 = (const float*)d_in[12];
    const float* Wc2 = (const float*)d_in[13];
    const float* bc2 = (const float*)d_in[14];
    const float* Wc3 = (const float*)d_in[15];
    const float* bc3 = (const float*)d_in[16];
    float* out = (float*)d_out;

    float* big  = SP(g_big);
    float* glo  = SP(g_glo);
    float* xt   = SP(g_xt);
    float* f1t  = SP(g_f1t);
    float* feat = SP(g_feat);
    float* cat  = SP(g_cat);
    float* xqt  = SP(g_xqt);
    float* xk   = SP(g_xk);
    float* cs   = SP(g_cs);
    float* xr   = SP(g_xr);
    float* tb   = SP(g_tb);
    float* ub   = SP(g_ub);
    float* fuse = SP(g_fuse);
    float* c0   = SP(g_c0);
    float* h1   = SP(g_h1);
    float* h2   = SP(g_h2);
    float* Wa1  = SP(g_Wa1); float* Wb1 = SP(g_Wb1);
    float* Wa2  = SP(g_Wa2); float* Wb2 = SP(g_Wb2);

    // ---- weight prep ----
    prep_w_k<<<16,256>>>(We1, We2);

    // ---- EdgeConv block 1 (C=3) ----
    xx1_k<<<dim3(NN/256,BB),256>>>(x);
    transpose3_k<<<dim3(NN/256,BB),256>>>(x);
    gram_df_t<3><<<dim3(NN/64,NN/64,BB),256>>>(xt, (long)NN*3, x, 3L*NN, big, glo);   // G1 (df)
    topk_df_k<<<dim3(NN,BB),256>>>();
    zero_stats_k<<<1,64>>>();
    ec_pass_t<3><<<dim3(NN,BB),256>>>(xt, Wa1, Wb1, be1);
    ec_fin_k<<<1,64>>>();
    ec_norm_k<<<dim3(NN/4,BB),256>>>(feat, f1t);                                      // f1 + f1t
    xx2_k<<<dim3(NN/256,BB),256>>>();

    // ---- EdgeConv block 2 (C=64) ----
    gram_df_t<64><<<dim3(NN/64,NN/64,BB),256>>>(f1t, (long)NN*64, feat, 128L*NN, big, glo); // G2 (df, symmetric)
    topk_df_k<<<dim3(NN,BB),256>>>();
    zero_stats_k<<<1,64>>>();
    ec_pass_t<64><<<dim3(NN,BB),256>>>(f1t, Wa2, Wb2, be2);
    ec_fin_k<<<1,64>>>();
    ec_norm_k<<<dim3(NN/4,BB),256>>>(feat + 64L*NN, (float*)0);                       // f2

    // ---- 4 SA layers ----
    for (int il=0; il<4; il++){
        const float* xin = (il==0)? feat : cat + (long)(il-1)*128*NN;
        long xs = (il==0)? 128L*NN : 512L*NN;
        sgemm(Wq+il*32*128,128,0, xin,NN,xs, xqt,32,32L*NN, 32,NN,128, 0,0,0,1);   // xq^T
        sgemm(Wk+il*32*128,128,0, xin,NN,xs, xk, NN,32L*NN, 32,NN,128, 0,0,0,0);   // xk
        sgemm(xqt,32,32L*NN, xk,NN,32L*NN, big,NN,(long)NN*NN, NN,NN,32, 0,0,0,0); // energy
        softmax_rows_k<<<dim3(NN,BB),256>>>();
        colsum_k<<<dim3(NN/256,BB),256>>>();
        sgemm(xin,NN,xs, big,NN,(long)NN*NN, xr,NN,128L*NN, 128,NN,NN, 0,0,cs,0);  // x@attn /(1e-6+cs)
        diff_k<<<(BB*128*NN)/256,256>>>(xin, xs, xr, tb);                          // t = x - xr
        sgemm(Wt+il*128*128,128,0, tb,NN,128L*NN, ub,NN,128L*NN, 128,NN,128, bt+il*128,0,0,0);
        stats_mean_k<<<128,256>>>(ub,128);
        stats_var_k<<<128,256>>>(ub,128);
        bn_relu_add_k<<<(BB*128*NN)/256,256>>>(ub, xin, xs, cat + (long)il*128*NN);
    }

    // ---- head ----
    sgemm(Wf,512,0, cat,NN,512L*NN, fuse,NN,1024L*NN, 1024,NN,512, bf,0,0,0);
    stats_mean_k<<<1024,256>>>(fuse,1024);
    stats_var_k<<<1024,256>>>(fuse,1024);
    bn_relu_k<<<(BB*1024*NN)/256,256>>>(fuse,fuse,1024);
    gmax_k<<<dim3(1024,BB),256>>>();
    c0_k<<<dim3(512,BB),256>>>(Wc1, bc1);
    sgemm(Wc1+1024,1536,0, cat,NN,512L*NN, h1,NN,512L*NN, 512,NN,512, 0,c0,0,0);
    stats_mean_k<<<512,256>>>(h1,512);
    stats_var_k<<<512,256>>>(h1,512);
    bn_relu_k<<<(BB*512*NN)/256,256>>>(h1,h1,512);
    sgemm(Wc2,512,0, h1,NN,512L*NN, h2,NN,256L*NN, 256,NN,512, bc2,0,0,0);
    stats_mean_k<<<256,256>>>(h2,256);
    stats_var_k<<<256,256>>>(h2,256);
    bn_relu_k<<<(BB*256*NN)/256,256>>>(h2,h2,256);
    sgemm(Wc3,256,0, h2,NN,256L*NN, out,NN,13L*NN, 13,NN,256, bc3,0,0,0);
}

// round 9
// speedup vs baseline: 1.3286x; 1.1284x over previous
#include <cuda_runtime.h>
#include <math.h>

#define BB 8
#define NN 2048
#define KK 32

// ---------------- scratch (device globals; no allocations) ----------------
__device__ float  g_big[BB*NN*NN];     // 134MB: G (knn) / energy / attn
__device__ int    g_idx[BB*NN*KK];
__device__ float  g_xt [BB*NN*3];
__device__ float  g_xx [BB*NN];
__device__ float  g_Wa1[3*64],  g_Wb1[3*64];    // transposed [c][o]
__device__ float  g_Wa2[64*64], g_Wb2[64*64];
__device__ float  g_m1t[BB*NN*64];
__device__ float  g_f1t[BB*NN*64];
__device__ float  g_feat[BB*128*NN];
__device__ float  g_cat [BB*512*NN];
__device__ float  g_xqt [BB*NN*32];
__device__ float  g_xk  [BB*32*NN];
__device__ float  g_cs  [BB*NN];
__device__ float  g_xr  [BB*128*NN];
__device__ float  g_tb  [BB*128*NN];
__device__ float  g_ub  [BB*128*NN];
__device__ float  g_fuse[BB*1024*NN];
__device__ float  g_gm  [BB*1024];
__device__ float  g_c0  [BB*512];
__device__ float  g_h1  [BB*512*NN];
__device__ float  g_h2  [BB*256*NN];
__device__ float  g_sum[64];
__device__ float  g_sumsq[64];
__device__ float  g_mean[1024];
__device__ float  g_rstd[1024];

// ---------------- double-float helpers ----------------
__device__ __forceinline__ void twoSum(float a, float b, float& s, float& e){
    s = __fadd_rn(a,b);
    float bb = __fsub_rn(s,a);
    e = __fadd_rn(__fsub_rn(a, __fsub_rn(s,bb)), __fsub_rn(b,bb));
}
__device__ __forceinline__ void dfMac(float& hi, float& lo, float a, float b){
    float p = __fmul_rn(a,b);
    float e = fmaf(a,b,-p);
    float s, err;
    twoSum(hi, p, s, err);
    lo = __fadd_rn(lo, __fadd_rn(err, e));
    float hi2 = __fadd_rn(s, lo);
    lo = __fsub_rn(lo, __fsub_rn(hi2, s));
    hi = hi2;
}

// ---------------- FMA-pipe exp (no MUFU), ~2ulp, x <= 0 ----------------
__device__ __forceinline__ float fast_exp(float x){
    float z  = fmaf(x, 1.442695041f, 12582912.0f);
    float nf = __fsub_rn(z, 12582912.0f);
    int   ni = (__float_as_int(z) & 0x7FFFFF) - 4194304;
    float r  = fmaf(nf, -0.693145751953125f, x);
    r = fmaf(nf, -1.42860677e-6f, r);
    float p = 1.9875691500e-4f;
    p = fmaf(p, r, 1.3981999507e-3f);
    p = fmaf(p, r, 8.3334519073e-3f);
    p = fmaf(p, r, 4.1665795894e-2f);
    p = fmaf(p, r, 1.6666665459e-1f);
    p = fmaf(p, r, 5.0000001201e-1f);
    float e = __fadd_rn(fmaf(__fmul_rn(r,r), p, r), 1.0f);
    if (ni < -126) ni = -126;
    float sc = __int_as_float((ni + 127) << 23);
    return __fmul_rn(e, sc);
}

// ---------------- templated tiled SGEMM (honest fp32) ----------------
// block tile = (16*RM) x 128, 256 threads, per-thread RM x 8
#define TBK 16
#define TBN 128

template<int RM>
__global__ void __launch_bounds__(256) sgemm_t(
    const float* __restrict__ A, int lda, long sA,
    const float* __restrict__ Bm, int ldb, long sB,
    float* __restrict__ C, int ldc, long sC,
    int M, int Nn, int Kd,
    const float* __restrict__ bias,
    const float* __restrict__ rowbias,
    const float* __restrict__ colscale,  // per-batch [Nn]: v /= (1e-6+cs)
    int transOut)
{
    const int TM = 16*RM;
    __shared__ float As[TBK][16*RM+4];
    __shared__ float Bs[TBK][TBN+4];
    int b = blockIdx.z;
    const float* Ab = A + (long)b*sA;
    const float* Bb = Bm + (long)b*sB;
    float* Cb = C + (long)b*sC;
    int m0 = blockIdx.y*TM, n0 = blockIdx.x*TBN;
    int tid = threadIdx.x;
    int tx = tid & 15, ty = tid >> 4;

    float acc[RM][8];
    #pragma unroll
    for (int i=0;i<RM;i++)
        #pragma unroll
        for (int j=0;j<8;j++) acc[i][j]=0.f;

    const int TPR = 16/RM;                 // threads covering the 16 k-cols of one A row
    int aRow  = tid / TPR;
    int aCol0 = (tid % TPR) * RM;
    int bRow  = tid >> 4;
    int bCol0 = (tid & 15) * 8;

    for (int k0 = 0; k0 < Kd; k0 += TBK) {
        #pragma unroll
        for (int j = 0; j < RM; j++) {
            int m = aRow, k = aCol0 + j;
            float v = 0.f;
            if (m0+m < M && k0+k < Kd) v = Ab[(long)(m0+m)*lda + k0+k];
            As[k][m] = v;
        }
        #pragma unroll
        for (int j = 0; j < 8; j++) {
            int k = bRow, n = bCol0 + j;
            float v = 0.f;
            if (k0+k < Kd && n0+n < Nn) v = Bb[(long)(k0+k)*ldb + n0+n];
            Bs[k][n] = v;
        }
        __syncthreads();
        #pragma unroll
        for (int kk = 0; kk < TBK; kk++) {
            float ra[RM], rb[8];
            if constexpr (RM >= 4){
                #pragma unroll
                for (int i4=0;i4<RM;i4+=4){
                    float4 a = *reinterpret_cast<const float4*>(&As[kk][ty*RM+i4]);
                    ra[i4]=a.x; ra[i4+1]=a.y; ra[i4+2]=a.z; ra[i4+3]=a.w;
                }
            } else {
                #pragma unroll
                for (int i=0;i<RM;i++) ra[i] = As[kk][ty*RM+i];
            }
            float4 b0 = *reinterpret_cast<const float4*>(&Bs[kk][tx*8]);
            float4 b1 = *reinterpret_cast<const float4*>(&Bs[kk][tx*8+4]);
            rb[0]=b0.x; rb[1]=b0.y; rb[2]=b0.z; rb[3]=b0.w;
            rb[4]=b1.x; rb[5]=b1.y; rb[6]=b1.z; rb[7]=b1.w;
            #pragma unroll
            for (int i=0;i<RM;i++)
                #pragma unroll
                for (int j=0;j<8;j++)
                    acc[i][j] = fmaf(ra[i], rb[j], acc[i][j]);
        }
        __syncthreads();
    }
    #pragma unroll
    for (int i=0;i<RM;i++){
        int row = m0 + ty*RM + i;
        if (row >= M) continue;
        float rb0 = 0.f;
        bool hasb = false;
        if (bias){    rb0 = __fadd_rn(rb0, bias[row]); hasb = true; }
        if (rowbias){ rb0 = __fadd_rn(rb0, rowbias[(long)b*M + row]); hasb = true; }
        #pragma unroll
        for (int j=0;j<8;j++){
            int col = n0 + tx*8 + j;
            if (col >= Nn) continue;
            float v = acc[i][j];
            if (hasb) v = __fadd_rn(v, rb0);
            if (colscale) v = __fdiv_rn(v, __fadd_rn(1e-6f, colscale[(long)b*Nn + col]));
            if (!transOut) Cb[(long)row*ldc + col] = v;
            else           Cb[(long)col*ldc + row] = v;   // ldc == M
        }
    }
}

// ---------------- small helpers ----------------
__global__ void prep_w_k(const float* __restrict__ We1, const float* __restrict__ We2)
{
    int i = blockIdx.x*256 + threadIdx.x;
    if (i < 64*3){ int o=i/3, c=i-o*3;
        g_Wa1[c*64+o] = We1[o*6+c];
        g_Wb1[c*64+o] = We1[o*6+3+c];
    }
    if (i < 64*64){ int o=i>>6, c=i&63;
        g_Wa2[c*64+o] = We2[o*128+c];
        g_Wb2[c*64+o] = We2[o*128+64+c];
    }
}

__global__ void transpose3_k(const float* __restrict__ x)
{
    int b=blockIdx.y; int n=blockIdx.x*256+threadIdx.x;
    #pragma unroll
    for (int c=0;c<3;c++)
        g_xt[((long)b*NN+n)*3+c] = x[(long)b*3*NN + (long)c*NN + n];
}

__global__ void xx1_k(const float* __restrict__ x)
{
    int b=blockIdx.y; int n=blockIdx.x*256+threadIdx.x;
    float s=0.f;
    #pragma unroll
    for (int c=0;c<3;c++){
        float v = x[(long)b*3*NN+(long)c*NN+n];
        s = __fadd_rn(s, __fmul_rn(v,v));
    }
    g_xx[b*NN+n]=s;
}

__global__ void xx2_k()   // from g_feat channels 0..63 (f1)
{
    int b=blockIdx.y; int n=blockIdx.x*256+threadIdx.x;
    const float* p = g_feat + (long)b*128*NN + n;
    float s=0.f;
    #pragma unroll 8
    for (int c=0;c<64;c++){
        float v = p[(long)c*NN];
        s = __fadd_rn(s, __fmul_rn(v,v));
    }
    g_xx[b*NN+n]=s;
}

// ---------------- kNN: fp32 top-32 + margin candidates + exact df re-rank ----------------
#define CCAP 192

template<int C>
__global__ void __launch_bounds__(256) topk_sel_t(const float* __restrict__ src)
{
    int b = blockIdx.y, n = blockIdx.x, t = threadIdx.x;
    const float* row = g_big + ((long)b*NN + n)*NN;
    const float* xxb = g_xx + (long)b*NN;
    float xxn = xxb[n];
    float lv[8];
    #pragma unroll
    for (int j=0;j<8;j++){
        int m = t + j*256;
        lv[j] = 2.f*row[m] - xxn - xxb[m];
    }
    __shared__ float s_v[8]; __shared__ int s_i[8]; __shared__ int s_win;
    __shared__ float s_v32;
    __shared__ int   scand[CCAP];
    __shared__ int   scnt;
    __shared__ float ch[CCAP], cl[CCAP];
    __shared__ float cen[C];

    // ---- stage 1: fp32 extraction of top-32 ----
    for (int kk=0; kk<KK; kk++){
        float bv = -INFINITY; int bi = 1<<30;
        #pragma unroll
        for (int j=0;j<8;j++){
            int m = t + j*256;
            float v = lv[j];
            if (v > bv || (v == bv && m < bi)) { bv = v; bi = m; }
        }
        #pragma unroll
        for (int off=16; off; off>>=1){
            float ov = __shfl_down_sync(0xffffffffu, bv, off);
            int   oi = __shfl_down_sync(0xffffffffu, bi, off);
            if (ov > bv || (ov == bv && oi < bi)) { bv=ov; bi=oi; }
        }
        if ((t&31)==0){ s_v[t>>5]=bv; s_i[t>>5]=bi; }
        __syncthreads();
        if (t < 32){
            if (t < 8){ bv = s_v[t]; bi = s_i[t]; } else { bv=-INFINITY; bi=1<<30; }
            #pragma unroll
            for (int off=4; off; off>>=1){
                float ov = __shfl_down_sync(0xffffffffu, bv, off);
                int   oi = __shfl_down_sync(0xffffffffu, bi, off);
                if (ov > bv || (ov == bv && oi < bi)) { bv=ov; bi=oi; }
            }
            if (t==0){ s_win = bi; scand[kk] = bi; if (kk==KK-1) s_v32 = bv; }
        }
        __syncthreads();
        int w = s_win;
        if ((w & 255) == t) lv[w>>8] = -INFINITY;
    }
    if (t==0) scnt = KK;
    __syncthreads();
    float v32 = s_v32;

    // ---- margin append: any index whose fp32 pdist could exceed true 32nd ----
    #pragma unroll
    for (int j=0;j<8;j++){
        if (lv[j] != -INFINITY){
            int m = t + j*256;
            float marg = fmaf(2e-4f, xxn + xxb[m], 1e-6f);
            if (lv[j] >= v32 - marg){
                int p = atomicAdd(&scnt, 1);
                if (p < CCAP) scand[p] = m;
            }
        }
    }
    if (t < C) cen[t] = src[((long)b*NN+n)*C + t];
    __syncthreads();
    int cnt = scnt < CCAP ? scnt : CCAP;

    // ---- stage 2: exact (double-float) squared distance per candidate ----
    if (t < cnt){
        int m = scand[t];
        const float* fm = src + ((long)b*NN+m)*C;
        float hi=0.f, lo=0.f;
        #pragma unroll 4
        for (int c=0;c<C;c++){
            float d = __fsub_rn(fm[c], cen[c]);
            dfMac(hi, lo, d, d);
        }
        ch[t]=hi; cl[t]=lo;
    }
    __syncthreads();

    // ---- exact rank (smaller d^2 better, tie -> smaller index); ranks unique ----
    if (t < cnt){
        int   mi = scand[t];
        float hi = ch[t], li = cl[t];
        int r = 0;
        for (int j=0;j<cnt;j++){
            float hj = ch[j], lj = cl[j];
            int   mj = scand[j];
            bool less = (hj < hi) || (hj == hi && (lj < li || (lj == li && mj < mi)));
            r += less;
        }
        if (r < KK) g_idx[((long)b*NN+n)*KK + r] = mi;
    }
}

// ---------------- EdgeConv: fused e + max-over-k + one-pass stats ----------------
template<int C>
__global__ void __launch_bounds__(256) ec_pass_t(
    const float* __restrict__ src,   // [B][NN][C] (n-major)
    const float* __restrict__ Wa,    // [C][64]
    const float* __restrict__ Wb,    // [C][64]
    const float* __restrict__ be)
{
    int b = blockIdx.y, n = blockIdx.x, t = threadIdx.x;
    __shared__ int   sidx[KK];
    __shared__ float cen[C];
    __shared__ float Was[C*64];
    __shared__ float Wbs[C*64];
    __shared__ float dr[KK][C + (C==64 ? 1 : 0)];
    __shared__ float sm[256], ss[256], ss2[256];

    const float* sb = src + (long)b*NN*C;
    if (t < KK) sidx[t] = g_idx[((long)b*NN+n)*KK + t];
    if (t < C)  cen[t] = sb[(long)n*C + t];
    for (int i=t; i<C*64; i+=256){ Was[i] = Wa[i]; Wbs[i] = Wb[i]; }
    __syncthreads();

    for (int i=t; i<KK*C; i+=256){
        int k = i/C, c = i - k*C;
        dr[k][c] = __fsub_rn(sb[(long)sidx[k]*C + c], cen[c]);
    }
    __syncthreads();

    int o = t & 63, kg = t >> 6;
    float bo = be[o];
    float mx = -INFINITY, s = 0.f, s2 = 0.f;
    #pragma unroll
    for (int j=0;j<8;j++){
        int k = kg*8 + j;
        float acc = 0.f;
        #pragma unroll
        for (int c=0;c<C;c++) acc = fmaf(Was[c*64+o], dr[k][c], acc);
        #pragma unroll
        for (int c=0;c<C;c++) acc = fmaf(Wbs[c*64+o], cen[c], acc);
        acc = __fadd_rn(acc, bo);
        mx = fmaxf(mx, acc);
        s += acc;
        s2 = fmaf(acc, acc, s2);
    }
    sm[t]=mx; ss[t]=s; ss2[t]=s2;
    __syncthreads();
    if (t < 128){ sm[t]=fmaxf(sm[t],sm[t+128]); ss[t]+=ss[t+128]; ss2[t]+=ss2[t+128]; }
    __syncthreads();
    if (t < 64){
        mx = fmaxf(sm[t],sm[t+64]); s = ss[t]+ss[t+64]; s2 = ss2[t]+ss2[t+64];
        g_m1t[((long)b*NN+n)*64 + t] = mx;
        atomicAdd(&g_sum[t], s);
        atomicAdd(&g_sumsq[t], s2);
    }
}

__global__ void zero_stats_k(){ int t=threadIdx.x; if (t<64){ g_sum[t]=0.f; g_sumsq[t]=0.f; } }

__global__ void ec_fin_k()
{
    int t=threadIdx.x;
    if (t<64){
        float cnt = (float)((long)BB*NN*KK);
        float m = g_sum[t]/cnt;
        float var = fmaxf(g_sumsq[t]/cnt - m*m, 0.f);
        g_mean[t]=m;
        g_rstd[t]=__fdiv_rn(1.f, __fsqrt_rn(__fadd_rn(var, 1e-5f)));
    }
}

__global__ void __launch_bounds__(256) ec_norm_k(float* __restrict__ featslice,
                                                 float* __restrict__ f1t)
{
    int b = blockIdx.y, t = threadIdx.x;
    int n = blockIdx.x*4 + (t>>6), c = t & 63;
    float v = g_m1t[((long)b*NN+n)*64 + c];
    v = fmaxf(__fmul_rn(__fsub_rn(v, g_mean[c]), g_rstd[c]), 0.f);
    featslice[(long)b*128*NN + (long)c*NN + n] = v;
    if (f1t) f1t[((long)b*NN+n)*64 + c] = v;
}

// ---------------- BN stats over [B][C][N]: deterministic two-pass, fp64 ----------------
__global__ void __launch_bounds__(256) stats_mean_k(const float* __restrict__ z, int C)
{
    int c = blockIdx.x, t = threadIdx.x;
    double s = 0.0;
    for (int i=t; i<BB*NN; i+=256){
        int b = i>>11, n = i&(NN-1);
        s += (double)z[((long)b*C + c)*NN + n];
    }
    __shared__ double sd[256];
    sd[t]=s; __syncthreads();
    for (int off=128; off; off>>=1){
        if (t<off) sd[t]+=sd[t+off];
        __syncthreads();
    }
    if (t==0) g_mean[c] = (float)(sd[0] / (double)(BB*NN));
}

__global__ void __launch_bounds__(256) stats_var_k(const float* __restrict__ z, int C)
{
    int c = blockIdx.x, t = threadIdx.x;
    float m = g_mean[c];
    double s = 0.0;
    for (int i=t; i<BB*NN; i+=256){
        int b = i>>11, n = i&(NN-1);
        float d = __fsub_rn(z[((long)b*C + c)*NN + n], m);
        s += (double)__fmul_rn(d,d);
    }
    __shared__ double sd[256];
    sd[t]=s; __syncthreads();
    for (int off=128; off; off>>=1){
        if (t<off) sd[t]+=sd[t+off];
        __syncthreads();
    }
    if (t==0){
        float var = (float)(sd[0] / (double)(BB*NN));
        g_rstd[c] = __fdiv_rn(1.f, __fsqrt_rn(__fadd_rn(var, 1e-5f)));
    }
}

__global__ void bn_relu_k(const float* __restrict__ z, float* __restrict__ o, int C)
{
    long i = (long)blockIdx.x*256 + threadIdx.x;
    int c = (int)((i>>11) & (C-1));
    float v = z[i];
    o[i] = fmaxf(__fmul_rn(__fsub_rn(v, g_mean[c]), g_rstd[c]), 0.f);
}

__global__ void bn_relu_add_k(const float* __restrict__ u, const float* __restrict__ xin,
                              long xs, float* __restrict__ o)
{
    long i = (long)blockIdx.x*256 + threadIdx.x;
    long b = i/(128L*NN); long r = i - b*128L*NN;
    int c = (int)((r>>11) & 127);
    float v = fmaxf(__fmul_rn(__fsub_rn(u[i], g_mean[c]), g_rstd[c]), 0.f);
    o[b*512L*NN + r] = __fadd_rn(xin[b*xs + r], v);
}

__global__ void diff_k(const float* __restrict__ xin, long xs,
                       const float* __restrict__ xr, float* __restrict__ o)
{
    long i = (long)blockIdx.x*256 + threadIdx.x;
    long b = i/(128L*NN); long r = i - b*128L*NN;
    o[i] = __fsub_rn(xin[b*xs + r], xr[i]);
}

// ---------------- attention softmax / colsum ----------------
__global__ void __launch_bounds__(256) softmax_rows_k()
{
    int b=blockIdx.y, n=blockIdx.x, t=threadIdx.x;
    float* row = g_big + ((long)b*NN+n)*NN;
    float lv[8]; float mx=-INFINITY;
    #pragma unroll
    for (int j=0;j<8;j++){ lv[j]=row[t+j*256]; mx=fmaxf(mx,lv[j]); }
    __shared__ float sw[8]; __shared__ float sbc;
    #pragma unroll
    for (int off=16;off;off>>=1) mx=fmaxf(mx,__shfl_xor_sync(0xffffffffu,mx,off));
    if ((t&31)==0) sw[t>>5]=mx;
    __syncthreads();
    if (t==0){ float m=sw[0]; for(int i=1;i<8;i++) m=fmaxf(m,sw[i]); sbc=m; }
    __syncthreads();
    mx = sbc;
    float s=0.f;
    #pragma unroll
    for (int j=0;j<8;j++){ lv[j]=fast_exp(__fsub_rn(lv[j],mx)); s=__fadd_rn(s,lv[j]); }
    #pragma unroll
    for (int off=16;off;off>>=1) s=__fadd_rn(s,__shfl_xor_sync(0xffffffffu,s,off));
    __syncthreads();
    if ((t&31)==0) sw[t>>5]=s;
    __syncthreads();
    if (t==0){ float m=0.f; for(int i=0;i<8;i++) m=__fadd_rn(m,sw[i]); sbc=m; }
    __syncthreads();
    float inv = __fdiv_rn(1.f, sbc);
    #pragma unroll
    for (int j=0;j<8;j++) row[t+j*256]=__fmul_rn(lv[j],inv);
}

__global__ void colsum_k()
{
    int b=blockIdx.y; int m=blockIdx.x*256+threadIdx.x;
    const float* p = g_big + (long)b*NN*NN + m;
    float s=0.f;
    #pragma unroll 8
    for (int nr=0; nr<NN; nr++) s = __fadd_rn(s, p[(long)nr*NN]);
    g_cs[b*NN+m]=s;
}

// ---------------- head ----------------
__global__ void gmax_k()
{
    int o=blockIdx.x, b=blockIdx.y, t=threadIdx.x;
    const float* p = g_fuse + ((long)b*1024 + o)*NN;
    float m=-INFINITY;
    for (int i=t;i<NN;i+=256) m=fmaxf(m,p[i]);
    __shared__ float sm[256]; sm[t]=m; __syncthreads();
    for (int off=128;off;off>>=1){ if(t<off) sm[t]=fmaxf(sm[t],sm[t+off]); __syncthreads(); }
    if (t==0) g_gm[b*1024+o]=sm[0];
}

__global__ void c0_k(const float* __restrict__ Wc1, const float* __restrict__ bc1)
{
    int o=blockIdx.x, b=blockIdx.y, t=threadIdx.x;
    float s=0.f;
    for (int c=t; c<1024; c+=256)
        s = fmaf(Wc1[(long)o*1536 + c], g_gm[b*1024+c], s);
    __shared__ float ss[256]; ss[t]=s; __syncthreads();
    for (int off=128;off;off>>=1){ if(t<off) ss[t]=__fadd_rn(ss[t],ss[t+off]); __syncthreads(); }
    if (t==0) g_c0[b*512+o]=__fadd_rn(ss[0],bc1[o]);
}

// ---------------- host ----------------
template<typename T, size_t NSZ>
static T* SP(T (&arr)[NSZ]){ void* p=nullptr; cudaGetSymbolAddress(&p, arr); return (T*)p; }

template<int RM>
static void sgemmT(const float* A,int lda,long sA,const float* B,int ldb,long sB,
                   float* C,int ldc,long sC,int M,int Nn,int Kd,
                   const float* bias,const float* rowbias,const float* colscale,int transOut)
{
    dim3 g((Nn+TBN-1)/TBN,(M+16*RM-1)/(16*RM),BB);
    sgemm_t<RM><<<g,256>>>(A,lda,sA,B,ldb,sB,C,ldc,sC,M,Nn,Kd,bias,rowbias,colscale,transOut);
}

extern "C" void kernel_launch(void* const* d_in, const int* in_sizes, int n_in,
                              void* d_out, int out_size)
{
    const float* x   = (const float*)d_in[0];
    const float* We1 = (const float*)d_in[1];
    const float* be1 = (const float*)d_in[2];
    const float* We2 = (const float*)d_in[3];
    const float* be2 = (const float*)d_in[4];
    const float* Wq  = (const float*)d_in[5];
    const float* Wk  = (const float*)d_in[6];
    const float* Wt  = (const float*)d_in[7];
    const float* bt  = (const float*)d_in[8];
    const float* Wf  = (const float*)d_in[9];
    const float* bf  = (const float*)d_in[10];
    const float* Wc1 = (const float*)d_in[11];
    const float* bc1 = (const float*)d_in[12];
    const float* Wc2 = (const float*)d_in[13];
    const float* bc2 = (const float*)d_in[14];
    const float* Wc3 = (const float*)d_in[15];
    const float* bc3 = (const float*)d_in[16];
    float* out = (float*)d_out;

    float* big  = SP(g_big);
    float* xt   = SP(g_xt);
    float* f1t  = SP(g_f1t);
    float* feat = SP(g_feat);
    float* cat  = SP(g_cat);
    float* xqt  = SP(g_xqt);
    float* xk   = SP(g_xk);
    float* cs   = SP(g_cs);
    float* xr   = SP(g_xr);
    float* tb   = SP(g_tb);
    float* ub   = SP(g_ub);
    float* fuse = SP(g_fuse);
    float* c0   = SP(g_c0);
    float* h1   = SP(g_h1);
    float* h2   = SP(g_h2);
    float* Wa1  = SP(g_Wa1); float* Wb1 = SP(g_Wb1);
    float* Wa2  = SP(g_Wa2); float* Wb2 = SP(g_Wb2);

    // ---- weight prep ----
    prep_w_k<<<16,256>>>(We1, We2);

    // ---- EdgeConv block 1 (C=3) ----
    xx1_k<<<dim3(NN/256,BB),256>>>(x);
    transpose3_k<<<dim3(NN/256,BB),256>>>(x);
    sgemmT<8>(xt,3,(long)NN*3, x,NN,3L*NN, big,NN,(long)NN*NN, NN,NN,3, 0,0,0,0);  // G1 fp32
    topk_sel_t<3><<<dim3(NN,BB),256>>>(xt);
    zero_stats_k<<<1,64>>>();
    ec_pass_t<3><<<dim3(NN,BB),256>>>(xt, Wa1, Wb1, be1);
    ec_fin_k<<<1,64>>>();
    ec_norm_k<<<dim3(NN/4,BB),256>>>(feat, f1t);                                   // f1 + f1t
    xx2_k<<<dim3(NN/256,BB),256>>>();

    // ---- EdgeConv block 2 (C=64) ----
    sgemmT<8>(f1t,64,64L*NN, feat,NN,128L*NN, big,NN,(long)NN*NN, NN,NN,64, 0,0,0,0); // G2 fp32
    topk_sel_t<64><<<dim3(NN,BB),256>>>(f1t);
    zero_stats_k<<<1,64>>>();
    ec_pass_t<64><<<dim3(NN,BB),256>>>(f1t, Wa2, Wb2, be2);
    ec_fin_k<<<1,64>>>();
    ec_norm_k<<<dim3(NN/4,BB),256>>>(feat + 64L*NN, (float*)0);                    // f2

    // ---- 4 SA layers ----
    for (int il=0; il<4; il++){
        const float* xin = (il==0)? feat : cat + (long)(il-1)*128*NN;
        long xs = (il==0)? 128L*NN : 512L*NN;
        sgemmT<2>(Wq+il*32*128,128,0, xin,NN,xs, xqt,32,32L*NN, 32,NN,128, 0,0,0,1);  // xq^T
        sgemmT<2>(Wk+il*32*128,128,0, xin,NN,xs, xk, NN,32L*NN, 32,NN,128, 0,0,0,0);  // xk
        sgemmT<8>(xqt,32,32L*NN, xk,NN,32L*NN, big,NN,(long)NN*NN, NN,NN,32, 0,0,0,0);// energy
        softmax_rows_k<<<dim3(NN,BB),256>>>();
        colsum_k<<<dim3(NN/256,BB),256>>>();
        sgemmT<4>(xin,NN,xs, big,NN,(long)NN*NN, xr,NN,128L*NN, 128,NN,NN, 0,0,cs,0); // x@attn /(1e-6+cs)
        diff_k<<<(BB*128*NN)/256,256>>>(xin, xs, xr, tb);                             // t = x - xr
        sgemmT<4>(Wt+il*128*128,128,0, tb,NN,128L*NN, ub,NN,128L*NN, 128,NN,128, bt+il*128,0,0,0);
        stats_mean_k<<<128,256>>>(ub,128);
        stats_var_k<<<128,256>>>(ub,128);
        bn_relu_add_k<<<(BB*128*NN)/256,256>>>(ub, xin, xs, cat + (long)il*128*NN);
    }

    // ---- head ----
    sgemmT<8>(Wf,512,0, cat,NN,512L*NN, fuse,NN,1024L*NN, 1024,NN,512, bf,0,0,0);
    stats_mean_k<<<1024,256>>>(fuse,1024);
    stats_var_k<<<1024,256>>>(fuse,1024);
    bn_relu_k<<<(BB*1024*NN)/256,256>>>(fuse,fuse,1024);
    gmax_k<<<dim3(1024,BB),256>>>();
    c0_k<<<dim3(512,BB),256>>>(Wc1, bc1);
    sgemmT<8>(Wc1+1024,1536,0, cat,NN,512L*NN, h1,NN,512L*NN, 512,NN,512, 0,c0,0,0);
    stats_mean_k<<<512,256>>>(h1,512);
    stats_var_k<<<512,256>>>(h1,512);
    bn_relu_k<<<(BB*512*NN)/256,256>>>(h1,h1,512);
    sgemmT<4>(Wc2,512,0, h1,NN,512L*NN, h2,NN,256L*NN, 256,NN,512, bc2,0,0,0);
    stats_mean_k<<<256,256>>>(h2,256);
    stats_var_k<<<256,256>>>(h2,256);
    bn_relu_k<<<(BB*256*NN)/256,256>>>(h2,h2,256);
    sgemmT<1>(Wc3,256,0, h2,NN,256L*NN, out,NN,13L*NN, 13,NN,256, bc3,0,0,0);
}

// round 11
// speedup vs baseline: 1.5395x; 1.1587x over previous
#include <cuda_runtime.h>
#include <math.h>

#define BB 8
#define NN 2048
#define KK 32

// ---------------- scratch (device globals; no allocations) ----------------
__device__ float  g_big[BB*NN*NN];     // 134MB: G (knn) / energy / attn
__device__ int    g_idx[BB*NN*KK];
__device__ float  g_xt [BB*NN*3];
__device__ float  g_xx [BB*NN];
__device__ float  g_Wa1[3*64],  g_Wb1[3*64];    // transposed [c][o]
__device__ float  g_Wa2[64*64], g_Wb2[64*64];
__device__ float  g_m1t[BB*NN*64];
__device__ float  g_f1t[BB*NN*64];
__device__ float  g_feat[BB*128*NN];
__device__ float  g_cat [BB*512*NN];
__device__ float  g_xqt [BB*NN*32];
__device__ float  g_xk  [BB*32*NN];
__device__ float  g_cs  [BB*NN];
__device__ float  g_xr  [BB*128*NN];
__device__ float  g_tb  [BB*128*NN];
__device__ float  g_ub  [BB*128*NN];
__device__ float  g_fuse[BB*1024*NN];
__device__ float  g_gm  [BB*1024];
__device__ float  g_c0  [BB*512];
__device__ float  g_h1  [BB*512*NN];
__device__ float  g_h2  [BB*256*NN];
__device__ float  g_sum[64];
__device__ float  g_sumsq[64];
__device__ float  g_mean[1024];
__device__ float  g_rstd[1024];

// ---------------- double-float helpers ----------------
__device__ __forceinline__ void twoSum(float a, float b, float& s, float& e){
    s = __fadd_rn(a,b);
    float bb = __fsub_rn(s,a);
    e = __fadd_rn(__fsub_rn(a, __fsub_rn(s,bb)), __fsub_rn(b,bb));
}
__device__ __forceinline__ void dfMac(float& hi, float& lo, float a, float b){
    float p = __fmul_rn(a,b);
    float e = fmaf(a,b,-p);
    float s, err;
    twoSum(hi, p, s, err);
    lo = __fadd_rn(lo, __fadd_rn(err, e));
    float hi2 = __fadd_rn(s, lo);
    lo = __fsub_rn(lo, __fsub_rn(hi2, s));
    hi = hi2;
}

// ---------------- FMA-pipe exp (no MUFU), ~2ulp, x <= 0 ----------------
__device__ __forceinline__ float fast_exp(float x){
    float z  = fmaf(x, 1.442695041f, 12582912.0f);
    float nf = __fsub_rn(z, 12582912.0f);
    int   ni = (__float_as_int(z) & 0x7FFFFF) - 4194304;
    float r  = fmaf(nf, -0.693145751953125f, x);
    r = fmaf(nf, -1.42860677e-6f, r);
    float p = 1.9875691500e-4f;
    p = fmaf(p, r, 1.3981999507e-3f);
    p = fmaf(p, r, 8.3334519073e-3f);
    p = fmaf(p, r, 4.1665795894e-2f);
    p = fmaf(p, r, 1.6666665459e-1f);
    p = fmaf(p, r, 5.0000001201e-1f);
    float e = __fadd_rn(fmaf(__fmul_rn(r,r), p, r), 1.0f);
    if (ni < -126) ni = -126;
    float sc = __int_as_float((ni + 127) << 23);
    return __fmul_rn(e, sc);
}

// ---------------- cp.async helpers ----------------
__device__ __forceinline__ void cp16(void* dst, const void* src){
    unsigned s = (unsigned)__cvta_generic_to_shared(dst);
    asm volatile("cp.async.ca.shared.global [%0], [%1], 16;" :: "r"(s), "l"(src) : "memory");
}
__device__ __forceinline__ void cp8(void* dst, const void* src){
    unsigned s = (unsigned)__cvta_generic_to_shared(dst);
    asm volatile("cp.async.ca.shared.global [%0], [%1], 8;" :: "r"(s), "l"(src) : "memory");
}
__device__ __forceinline__ void cp_commit(){ asm volatile("cp.async.commit_group;" ::: "memory"); }
template<int N>
__device__ __forceinline__ void cp_wait(){ asm volatile("cp.async.wait_group %0;" :: "n"(N) : "memory"); }

// ---------------- BIG GEMM: no bounds, cp.async double-buffered ----------------
// Requires: Nn%128==0, Kd%16==0, M%(16*RM)==0, lda%4==0, ldb%4==0
#define TBK 16
#define TBN 128

template<int RM>
__global__ void __launch_bounds__(256) bgemm_t(
    const float* __restrict__ A, int lda, long sA,
    const float* __restrict__ Bm, int ldb, long sB,
    float* __restrict__ C, int ldc, long sC,
    int M, int Nn, int Kd,
    const float* __restrict__ bias,
    const float* __restrict__ rowbias,
    const float* __restrict__ colscale,
    int transOut)
{
    const int TM = 16*RM;
    __shared__ float As[2][16*RM][20];     // [row][k], stride 20 (16B-aligned, odd banks)
    __shared__ float Bs[2][TBK][132];      // [k][n]
    int b = blockIdx.z;
    const float* Ab = A + (long)b*sA;
    const float* Bb = Bm + (long)b*sB;
    float* Cb = C + (long)b*sC;
    int m0 = blockIdx.y*TM, n0 = blockIdx.x*TBN;
    int tid = threadIdx.x;
    int tx = tid & 15, ty = tid >> 4;

    float acc[RM][8];
    #pragma unroll
    for (int i=0;i<RM;i++)
        #pragma unroll
        for (int j=0;j<8;j++) acc[i][j]=0.f;

    int KT = Kd / TBK;

    auto prefetch = [&](int kt, int buf){
        int k0 = kt*TBK;
        if (RM == 8){
            int row = tid >> 1, off = (tid & 1) * 8;
            const float* src = Ab + (long)(m0+row)*lda + k0 + off;
            cp16(&As[buf][row][off],   src);
            cp16(&As[buf][row][off+4], src+4);
        } else if (RM == 4){
            int row = tid >> 2, off = (tid & 3) * 4;
            cp16(&As[buf][row][off], Ab + (long)(m0+row)*lda + k0 + off);
        } else { // RM == 2
            int row = tid >> 3, off = (tid & 7) * 2;
            cp8(&As[buf][row][off], Ab + (long)(m0+row)*lda + k0 + off);
        }
        {
            int krow = tid >> 4, cseg = tid & 15;
            const float* src = Bb + (long)(k0+krow)*ldb + n0 + cseg*8;
            cp16(&Bs[buf][krow][cseg*8],   src);
            cp16(&Bs[buf][krow][cseg*8+4], src+4);
        }
    };

    prefetch(0, 0);
    cp_commit();

    for (int kt = 0; kt < KT; kt++){
        int buf = kt & 1;
        if (kt+1 < KT){
            prefetch(kt+1, (kt+1)&1);
            cp_commit();
            cp_wait<1>();
        } else {
            cp_wait<0>();
        }
        __syncthreads();
        #pragma unroll
        for (int kk = 0; kk < TBK; kk++){
            float ra[RM], rb[8];
            #pragma unroll
            for (int i=0;i<RM;i++) ra[i] = As[buf][ty*RM+i][kk];
            float4 b0 = *reinterpret_cast<const float4*>(&Bs[buf][kk][tx*8]);
            float4 b1 = *reinterpret_cast<const float4*>(&Bs[buf][kk][tx*8+4]);
            rb[0]=b0.x; rb[1]=b0.y; rb[2]=b0.z; rb[3]=b0.w;
            rb[4]=b1.x; rb[5]=b1.y; rb[6]=b1.z; rb[7]=b1.w;
            #pragma unroll
            for (int i=0;i<RM;i++)
                #pragma unroll
                for (int j=0;j<8;j++)
                    acc[i][j] = fmaf(ra[i], rb[j], acc[i][j]);
        }
        __syncthreads();
    }

    #pragma unroll
    for (int i=0;i<RM;i++){
        int row = m0 + ty*RM + i;
        float rb0 = 0.f;
        bool hasb = false;
        if (bias){    rb0 = __fadd_rn(rb0, bias[row]); hasb = true; }
        if (rowbias){ rb0 = __fadd_rn(rb0, rowbias[(long)b*M + row]); hasb = true; }
        #pragma unroll
        for (int j=0;j<8;j++){
            int col = n0 + tx*8 + j;
            float v = acc[i][j];
            if (hasb) v = __fadd_rn(v, rb0);
            if (colscale) v = __fdiv_rn(v, __fadd_rn(1e-6f, colscale[(long)b*Nn + col]));
            if (!transOut) Cb[(long)row*ldc + col] = v;
            else           Cb[(long)col*ldc + row] = v;
        }
    }
}

// ---------------- generic checked SGEMM (for K=3 / M=13 cases) ----------------
template<int RM>
__global__ void __launch_bounds__(256) sgemm_t(
    const float* __restrict__ A, int lda, long sA,
    const float* __restrict__ Bm, int ldb, long sB,
    float* __restrict__ C, int ldc, long sC,
    int M, int Nn, int Kd,
    const float* __restrict__ bias,
    const float* __restrict__ rowbias,
    const float* __restrict__ colscale,
    int transOut)
{
    const int TM = 16*RM;
    __shared__ float As[TBK][16*RM+4];
    __shared__ float Bs[TBK][TBN+4];
    int b = blockIdx.z;
    const float* Ab = A + (long)b*sA;
    const float* Bb = Bm + (long)b*sB;
    float* Cb = C + (long)b*sC;
    int m0 = blockIdx.y*TM, n0 = blockIdx.x*TBN;
    int tid = threadIdx.x;
    int tx = tid & 15, ty = tid >> 4;

    float acc[RM][8];
    #pragma unroll
    for (int i=0;i<RM;i++)
        #pragma unroll
        for (int j=0;j<8;j++) acc[i][j]=0.f;

    const int TPR = 16/RM;
    int aRow  = tid / TPR;
    int aCol0 = (tid % TPR) * RM;
    int bRow  = tid >> 4;
    int bCol0 = (tid & 15) * 8;

    for (int k0 = 0; k0 < Kd; k0 += TBK) {
        #pragma unroll
        for (int j = 0; j < RM; j++) {
            int m = aRow, k = aCol0 + j;
            float v = 0.f;
            if (m0+m < M && k0+k < Kd) v = Ab[(long)(m0+m)*lda + k0+k];
            As[k][m] = v;
        }
        #pragma unroll
        for (int j = 0; j < 8; j++) {
            int k = bRow, n = bCol0 + j;
            float v = 0.f;
            if (k0+k < Kd && n0+n < Nn) v = Bb[(long)(k0+k)*ldb + n0+n];
            Bs[k][n] = v;
        }
        __syncthreads();
        #pragma unroll
        for (int kk = 0; kk < TBK; kk++) {
            float ra[RM], rb[8];
            #pragma unroll
            for (int i=0;i<RM;i++) ra[i] = As[kk][ty*RM+i];
            float4 b0 = *reinterpret_cast<const float4*>(&Bs[kk][tx*8]);
            float4 b1 = *reinterpret_cast<const float4*>(&Bs[kk][tx*8+4]);
            rb[0]=b0.x; rb[1]=b0.y; rb[2]=b0.z; rb[3]=b0.w;
            rb[4]=b1.x; rb[5]=b1.y; rb[6]=b1.z; rb[7]=b1.w;
            #pragma unroll
            for (int i=0;i<RM;i++)
                #pragma unroll
                for (int j=0;j<8;j++)
                    acc[i][j] = fmaf(ra[i], rb[j], acc[i][j]);
        }
        __syncthreads();
    }
    #pragma unroll
    for (int i=0;i<RM;i++){
        int row = m0 + ty*RM + i;
        if (row >= M) continue;
        float rb0 = 0.f;
        bool hasb = false;
        if (bias){    rb0 = __fadd_rn(rb0, bias[row]); hasb = true; }
        if (rowbias){ rb0 = __fadd_rn(rb0, rowbias[(long)b*M + row]); hasb = true; }
        #pragma unroll
        for (int j=0;j<8;j++){
            int col = n0 + tx*8 + j;
            if (col >= Nn) continue;
            float v = acc[i][j];
            if (hasb) v = __fadd_rn(v, rb0);
            if (colscale) v = __fdiv_rn(v, __fadd_rn(1e-6f, colscale[(long)b*Nn + col]));
            if (!transOut) Cb[(long)row*ldc + col] = v;
            else           Cb[(long)col*ldc + row] = v;
        }
    }
}

// ---------------- small helpers ----------------
__global__ void prep_w_k(const float* __restrict__ We1, const float* __restrict__ We2)
{
    int i = blockIdx.x*256 + threadIdx.x;
    if (i < 64*3){ int o=i/3, c=i-o*3;
        g_Wa1[c*64+o] = We1[o*6+c];
        g_Wb1[c*64+o] = We1[o*6+3+c];
    }
    if (i < 64*64){ int o=i>>6, c=i&63;
        g_Wa2[c*64+o] = We2[o*128+c];
        g_Wb2[c*64+o] = We2[o*128+64+c];
    }
}

__global__ void transpose3_k(const float* __restrict__ x)
{
    int b=blockIdx.y; int n=blockIdx.x*256+threadIdx.x;
    #pragma unroll
    for (int c=0;c<3;c++)
        g_xt[((long)b*NN+n)*3+c] = x[(long)b*3*NN + (long)c*NN + n];
}

__global__ void xx1_k(const float* __restrict__ x)
{
    int b=blockIdx.y; int n=blockIdx.x*256+threadIdx.x;
    float s=0.f;
    #pragma unroll
    for (int c=0;c<3;c++){
        float v = x[(long)b*3*NN+(long)c*NN+n];
        s = __fadd_rn(s, __fmul_rn(v,v));
    }
    g_xx[b*NN+n]=s;
}

__global__ void xx2_k()
{
    int b=blockIdx.y; int n=blockIdx.x*256+threadIdx.x;
    const float* p = g_feat + (long)b*128*NN + n;
    float s=0.f;
    #pragma unroll 8
    for (int c=0;c<64;c++){
        float v = p[(long)c*NN];
        s = __fadd_rn(s, __fmul_rn(v,v));
    }
    g_xx[b*NN+n]=s;
}

// ---------------- kNN: fp32 top-32 + margin candidates + exact df re-rank ----------------
#define CCAP 192

template<int C>
__global__ void __launch_bounds__(256) topk_sel_t(const float* __restrict__ src)
{
    int b = blockIdx.y, n = blockIdx.x, t = threadIdx.x;
    const float* row = g_big + ((long)b*NN + n)*NN;
    const float* xxb = g_xx + (long)b*NN;
    float xxn = xxb[n];
    float lv[8];
    #pragma unroll
    for (int j=0;j<8;j++){
        int m = t + j*256;
        lv[j] = 2.f*row[m] - xxn - xxb[m];
    }
    __shared__ float s_v[8]; __shared__ int s_i[8]; __shared__ int s_win;
    __shared__ float s_v32;
    __shared__ int   scand[CCAP];
    __shared__ int   scnt;
    __shared__ float ch[CCAP], cl[CCAP];
    __shared__ float cen[C];

    for (int kk=0; kk<KK; kk++){
        float bv = -INFINITY; int bi = 1<<30;
        #pragma unroll
        for (int j=0;j<8;j++){
            int m = t + j*256;
            float v = lv[j];
            if (v > bv || (v == bv && m < bi)) { bv = v; bi = m; }
        }
        #pragma unroll
        for (int off=16; off; off>>=1){
            float ov = __shfl_down_sync(0xffffffffu, bv, off);
            int   oi = __shfl_down_sync(0xffffffffu, bi, off);
            if (ov > bv || (ov == bv && oi < bi)) { bv=ov; bi=oi; }
        }
        if ((t&31)==0){ s_v[t>>5]=bv; s_i[t>>5]=bi; }
        __syncthreads();
        if (t < 32){
            if (t < 8){ bv = s_v[t]; bi = s_i[t]; } else { bv=-INFINITY; bi=1<<30; }
            #pragma unroll
            for (int off=4; off; off>>=1){
                float ov = __shfl_down_sync(0xffffffffu, bv, off);
                int   oi = __shfl_down_sync(0xffffffffu, bi, off);
                if (ov > bv || (ov == bv && oi < bi)) { bv=ov; bi=oi; }
            }
            if (t==0){ s_win = bi; scand[kk] = bi; if (kk==KK-1) s_v32 = bv; }
        }
        __syncthreads();
        int w = s_win;
        if ((w & 255) == t) lv[w>>8] = -INFINITY;
    }
    if (t==0) scnt = KK;
    __syncthreads();
    float v32 = s_v32;

    #pragma unroll
    for (int j=0;j<8;j++){
        if (lv[j] != -INFINITY){
            int m = t + j*256;
            float marg = fmaf(2e-4f, xxn + xxb[m], 1e-6f);
            if (lv[j] >= v32 - marg){
                int p = atomicAdd(&scnt, 1);
                if (p < CCAP) scand[p] = m;
            }
        }
    }
    if (t < C) cen[t] = src[((long)b*NN+n)*C + t];
    __syncthreads();
    int cnt = scnt < CCAP ? scnt : CCAP;

    if (t < cnt){
        int m = scand[t];
        const float* fm = src + ((long)b*NN+m)*C;
        float hi=0.f, lo=0.f;
        #pragma unroll 4
        for (int c=0;c<C;c++){
            float d = __fsub_rn(fm[c], cen[c]);
            dfMac(hi, lo, d, d);
        }
        ch[t]=hi; cl[t]=lo;
    }
    __syncthreads();

    if (t < cnt){
        int   mi = scand[t];
        float hi = ch[t], li = cl[t];
        int r = 0;
        for (int j=0;j<cnt;j++){
            float hj = ch[j], lj = cl[j];
            int   mj = scand[j];
            bool less = (hj < hi) || (hj == hi && (lj < li || (lj == li && mj < mi)));
            r += less;
        }
        if (r < KK) g_idx[((long)b*NN+n)*KK + r] = mi;
    }
}

// ---------------- EdgeConv: fused e + max-over-k + one-pass stats ----------------
template<int C>
__global__ void __launch_bounds__(256) ec_pass_t(
    const float* __restrict__ src,
    const float* __restrict__ Wa,
    const float* __restrict__ Wb,
    const float* __restrict__ be)
{
    int b = blockIdx.y, n = blockIdx.x, t = threadIdx.x;
    __shared__ int   sidx[KK];
    __shared__ float cen[C];
    __shared__ float Was[C*64];
    __shared__ float Wbs[C*64];
    __shared__ float dr[KK][C + (C==64 ? 1 : 0)];
    __shared__ float t1s[64];
    __shared__ float sm[256], ss[256], ss2[256];

    const float* sb = src + (long)b*NN*C;
    if (t < KK) sidx[t] = g_idx[((long)b*NN+n)*KK + t];
    if (t < C)  cen[t] = sb[(long)n*C + t];
    for (int i=t; i<C*64; i+=256){ Was[i] = Wa[i]; Wbs[i] = Wb[i]; }
    __syncthreads();

    if (t < 64){
        float a = 0.f;
        #pragma unroll
        for (int c=0;c<C;c++) a = fmaf(Wbs[c*64+t], cen[c], a);
        t1s[t] = __fadd_rn(a, be[t]);
    }
    for (int i=t; i<KK*C; i+=256){
        int k = i/C, c = i - k*C;
        dr[k][c] = __fsub_rn(sb[(long)sidx[k]*C + c], cen[c]);
    }
    __syncthreads();

    int o = t & 63, kg = t >> 6;
    float t1 = t1s[o];
    float mx = -INFINITY, s = 0.f, s2 = 0.f;
    #pragma unroll
    for (int j=0;j<8;j++){
        int k = kg*8 + j;
        float acc = 0.f;
        #pragma unroll
        for (int c=0;c<C;c++) acc = fmaf(Was[c*64+o], dr[k][c], acc);
        acc = __fadd_rn(acc, t1);
        mx = fmaxf(mx, acc);
        s += acc;
        s2 = fmaf(acc, acc, s2);
    }
    sm[t]=mx; ss[t]=s; ss2[t]=s2;
    __syncthreads();
    if (t < 128){ sm[t]=fmaxf(sm[t],sm[t+128]); ss[t]+=ss[t+128]; ss2[t]+=ss2[t+128]; }
    __syncthreads();
    if (t < 64){
        mx = fmaxf(sm[t],sm[t+64]); s = ss[t]+ss[t+64]; s2 = ss2[t]+ss2[t+64];
        g_m1t[((long)b*NN+n)*64 + t] = mx;
        atomicAdd(&g_sum[t], s);
        atomicAdd(&g_sumsq[t], s2);
    }
}

__global__ void zero_stats_k(){ int t=threadIdx.x; if (t<64){ g_sum[t]=0.f; g_sumsq[t]=0.f; } }

__global__ void ec_fin_k()
{
    int t=threadIdx.x;
    if (t<64){
        float cnt = (float)((long)BB*NN*KK);
        float m = g_sum[t]/cnt;
        float var = fmaxf(g_sumsq[t]/cnt - m*m, 0.f);
        g_mean[t]=m;
        g_rstd[t]=__fdiv_rn(1.f, __fsqrt_rn(__fadd_rn(var, 1e-5f)));
    }
}

__global__ void __launch_bounds__(256) ec_norm_k(float* __restrict__ featslice,
                                                 float* __restrict__ f1t)
{
    int b = blockIdx.y, t = threadIdx.x;
    int n = blockIdx.x*4 + (t>>6), c = t & 63;
    float v = g_m1t[((long)b*NN+n)*64 + c];
    v = fmaxf(__fmul_rn(__fsub_rn(v, g_mean[c]), g_rstd[c]), 0.f);
    featslice[(long)b*128*NN + (long)c*NN + n] = v;
    if (f1t) f1t[((long)b*NN+n)*64 + c] = v;
}

// ---------------- BN stats over [B][C][N]: deterministic two-pass, fp64 ----------------
__global__ void __launch_bounds__(256) stats_mean_k(const float* __restrict__ z, int C)
{
    int c = blockIdx.x, t = threadIdx.x;
    double s = 0.0;
    for (int i=t; i<BB*NN; i+=256){
        int b = i>>11, n = i&(NN-1);
        s += (double)z[((long)b*C + c)*NN + n];
    }
    __shared__ double sd[256];
    sd[t]=s; __syncthreads();
    for (int off=128; off; off>>=1){
        if (t<off) sd[t]+=sd[t+off];
        __syncthreads();
    }
    if (t==0) g_mean[c] = (float)(sd[0] / (double)(BB*NN));
}

__global__ void __launch_bounds__(256) stats_var_k(const float* __restrict__ z, int C)
{
    int c = blockIdx.x, t = threadIdx.x;
    float m = g_mean[c];
    double s = 0.0;
    for (int i=t; i<BB*NN; i+=256){
        int b = i>>11, n = i&(NN-1);
        float d = __fsub_rn(z[((long)b*C + c)*NN + n], m);
        s += (double)__fmul_rn(d,d);
    }
    __shared__ double sd[256];
    sd[t]=s; __syncthreads();
    for (int off=128; off; off>>=1){
        if (t<off) sd[t]+=sd[t+off];
        __syncthreads();
    }
    if (t==0){
        float var = (float)(sd[0] / (double)(BB*NN));
        g_rstd[c] = __fdiv_rn(1.f, __fsqrt_rn(__fadd_rn(var, 1e-5f)));
    }
}

__global__ void bn_relu_k(const float* __restrict__ z, float* __restrict__ o, int C)
{
    long i = (long)blockIdx.x*256 + threadIdx.x;
    int c = (int)((i>>11) & (C-1));
    float v = z[i];
    o[i] = fmaxf(__fmul_rn(__fsub_rn(v, g_mean[c]), g_rstd[c]), 0.f);
}

__global__ void bn_relu_add_k(const float* __restrict__ u, const float* __restrict__ xin,
                              long xs, float* __restrict__ o)
{
    long i = (long)blockIdx.x*256 + threadIdx.x;
    long b = i/(128L*NN); long r = i - b*128L*NN;
    int c = (int)((r>>11) & 127);
    float v = fmaxf(__fmul_rn(__fsub_rn(u[i], g_mean[c]), g_rstd[c]), 0.f);
    o[b*512L*NN + r] = __fadd_rn(xin[b*xs + r], v);
}

__global__ void diff_k(const float* __restrict__ xin, long xs,
                       const float* __restrict__ xr, float* __restrict__ o)
{
    long i = (long)blockIdx.x*256 + threadIdx.x;
    long b = i/(128L*NN); long r = i - b*128L*NN;
    o[i] = __fsub_rn(xin[b*xs + r], xr[i]);
}

// ---------------- attention softmax / colsum ----------------
__global__ void __launch_bounds__(256) softmax_rows_k()
{
    int b=blockIdx.y, n=blockIdx.x, t=threadIdx.x;
    float* row = g_big + ((long)b*NN+n)*NN;
    float lv[8]; float mx=-INFINITY;
    #pragma unroll
    for (int j=0;j<8;j++){ lv[j]=row[t+j*256]; mx=fmaxf(mx,lv[j]); }
    __shared__ float sw[8]; __shared__ float sbc;
    #pragma unroll
    for (int off=16;off;off>>=1) mx=fmaxf(mx,__shfl_xor_sync(0xffffffffu,mx,off));
    if ((t&31)==0) sw[t>>5]=mx;
    __syncthreads();
    if (t==0){ float m=sw[0]; for(int i=1;i<8;i++) m=fmaxf(m,sw[i]); sbc=m; }
    __syncthreads();
    mx = sbc;
    float s=0.f;
    #pragma unroll
    for (int j=0;j<8;j++){ lv[j]=fast_exp(__fsub_rn(lv[j],mx)); s=__fadd_rn(s,lv[j]); }
    #pragma unroll
    for (int off=16;off;off>>=1) s=__fadd_rn(s,__shfl_xor_sync(0xffffffffu,s,off));
    __syncthreads();
    if ((t&31)==0) sw[t>>5]=s;
    __syncthreads();
    if (t==0){ float m=0.f; for(int i=0;i<8;i++) m=__fadd_rn(m,sw[i]); sbc=m; }
    __syncthreads();
    float inv = __fdiv_rn(1.f, sbc);
    #pragma unroll
    for (int j=0;j<8;j++) row[t+j*256]=__fmul_rn(lv[j],inv);
}

__global__ void colsum_k()
{
    int b=blockIdx.y; int m=blockIdx.x*256+threadIdx.x;
    const float* p = g_big + (long)b*NN*NN + m;
    float s=0.f;
    #pragma unroll 8
    for (int nr=0; nr<NN; nr++) s = __fadd_rn(s, p[(long)nr*NN]);
    g_cs[b*NN+m]=s;
}

// ---------------- head ----------------
__global__ void gmax_k()
{
    int o=blockIdx.x, b=blockIdx.y, t=threadIdx.x;
    const float* p = g_fuse + ((long)b*1024 + o)*NN;
    float m=-INFINITY;
    for (int i=t;i<NN;i+=256) m=fmaxf(m,p[i]);
    __shared__ float sm[256]; sm[t]=m; __syncthreads();
    for (int off=128;off;off>>=1){ if(t<off) sm[t]=fmaxf(sm[t],sm[t+off]); __syncthreads(); }
    if (t==0) g_gm[b*1024+o]=sm[0];
}

__global__ void c0_k(const float* __restrict__ Wc1, const float* __restrict__ bc1)
{
    int o=blockIdx.x, b=blockIdx.y, t=threadIdx.x;
    float s=0.f;
    for (int c=t; c<1024; c+=256)
        s = fmaf(Wc1[(long)o*1536 + c], g_gm[b*1024+c], s);
    __shared__ float ss[256]; ss[t]=s; __syncthreads();
    for (int off=128;off;off>>=1){ if(t<off) ss[t]=__fadd_rn(ss[t],ss[t+off]); __syncthreads(); }
    if (t==0) g_c0[b*512+o]=__fadd_rn(ss[0],bc1[o]);
}

// ---------------- host ----------------
template<typename T, size_t NSZ>
static T* SP(T (&arr)[NSZ]){ void* p=nullptr; cudaGetSymbolAddress(&p, arr); return (T*)p; }

template<int RM>
static void sgemmT(const float* A,int lda,long sA,const float* B,int ldb,long sB,
                   float* C,int ldc,long sC,int M,int Nn,int Kd,
                   const float* bias,const float* rowbias,const float* colscale,int transOut)
{
    dim3 g((Nn+TBN-1)/TBN,(M+16*RM-1)/(16*RM),BB);
    sgemm_t<RM><<<g,256>>>(A,lda,sA,B,ldb,sB,C,ldc,sC,M,Nn,Kd,bias,rowbias,colscale,transOut);
}

template<int RM>
static void bgemmT(const float* A,int lda,long sA,const float* B,int ldb,long sB,
                   float* C,int ldc,long sC,int M,int Nn,int Kd,
                   const float* bias,const float* rowbias,const float* colscale,int transOut)
{
    dim3 g(Nn/TBN, M/(16*RM), BB);
    bgemm_t<RM><<<g,256>>>(A,lda,sA,B,ldb,sB,C,ldc,sC,M,Nn,Kd,bias,rowbias,colscale,transOut);
}

extern "C" void kernel_launch(void* const* d_in, const int* in_sizes, int n_in,
                              void* d_out, int out_size)
{
    const float* x   = (const float*)d_in[0];
    const float* We1 = (const float*)d_in[1];
    const float* be1 = (const float*)d_in[2];
    const float* We2 = (const float*)d_in[3];
    const float* be2 = (const float*)d_in[4];
    const float* Wq  = (const float*)d_in[5];
    const float* Wk  = (const float*)d_in[6];
    const float* Wt  = (const float*)d_in[7];
    const float* bt  = (const float*)d_in[8];
    const float* Wf  = (const float*)d_in[9];
    const float* bf  = (const float*)d_in[10];
    const float* Wc1 = (const float*)d_in[11];
    const float* bc1 = (const float*)d_in[12];
    const float* Wc2 = (const float*)d_in[13];
    const float* bc2 = (const float*)d_in[14];
    const float* Wc3 = (const float*)d_in[15];
    const float* bc3 = (const float*)d_in[16];
    float* out = (float*)d_out;

    float* big  = SP(g_big);
    float* xt   = SP(g_xt);
    float* f1t  = SP(g_f1t);
    float* feat = SP(g_feat);
    float* cat  = SP(g_cat);
    float* xqt  = SP(g_xqt);
    float* xk   = SP(g_xk);
    float* cs   = SP(g_cs);
    float* xr   = SP(g_xr);
    float* tb   = SP(g_tb);
    float* ub   = SP(g_ub);
    float* fuse = SP(g_fuse);
    float* c0   = SP(g_c0);
    float* h1   = SP(g_h1);
    float* h2   = SP(g_h2);
    float* Wa1  = SP(g_Wa1); float* Wb1 = SP(g_Wb1);
    float* Wa2  = SP(g_Wa2); float* Wb2 = SP(g_Wb2);

    // ---- weight prep ----
    prep_w_k<<<16,256>>>(We1, We2);

    // ---- EdgeConv block 1 (C=3) ----
    xx1_k<<<dim3(NN/256,BB),256>>>(x);
    transpose3_k<<<dim3(NN/256,BB),256>>>(x);
    sgemmT<8>(xt,3,(long)NN*3, x,NN,3L*NN, big,NN,(long)NN*NN, NN,NN,3, 0,0,0,0);  // G1 (K=3, checked)
    topk_sel_t<3><<<dim3(NN,BB),256>>>(xt);
    zero_stats_k<<<1,64>>>();
    ec_pass_t<3><<<dim3(NN,BB),256>>>(xt, Wa1, Wb1, be1);
    ec_fin_k<<<1,64>>>();
    ec_norm_k<<<dim3(NN/4,BB),256>>>(feat, f1t);
    xx2_k<<<dim3(NN/256,BB),256>>>();

    // ---- EdgeConv block 2 (C=64) ----
    bgemmT<8>(f1t,64,64L*NN, feat,NN,128L*NN, big,NN,(long)NN*NN, NN,NN,64, 0,0,0,0); // G2
    topk_sel_t<64><<<dim3(NN,BB),256>>>(f1t);
    zero_stats_k<<<1,64>>>();
    ec_pass_t<64><<<dim3(NN,BB),256>>>(f1t, Wa2, Wb2, be2);
    ec_fin_k<<<1,64>>>();
    ec_norm_k<<<dim3(NN/4,BB),256>>>(feat + 64L*NN, (float*)0);

    // ---- 4 SA layers ----
    for (int il=0; il<4; il++){
        const float* xin = (il==0)? feat : cat + (long)(il-1)*128*NN;
        long xs = (il==0)? 128L*NN : 512L*NN;
        bgemmT<2>(Wq+il*32*128,128,0, xin,NN,xs, xqt,32,32L*NN, 32,NN,128, 0,0,0,1);   // xq^T
        bgemmT<2>(Wk+il*32*128,128,0, xin,NN,xs, xk, NN,32L*NN, 32,NN,128, 0,0,0,0);   // xk
        bgemmT<8>(xqt,32,32L*NN, xk,NN,32L*NN, big,NN,(long)NN*NN, NN,NN,32, 0,0,0,0); // energy
        softmax_rows_k<<<dim3(NN,BB),256>>>();
        colsum_k<<<dim3(NN/256,BB),256>>>();
        bgemmT<4>(xin,NN,xs, big,NN,(long)NN*NN, xr,NN,128L*NN, 128,NN,NN, 0,0,cs,0);  // x@attn
        diff_k<<<(BB*128*NN)/256,256>>>(xin, xs, xr, tb);
        bgemmT<4>(Wt+il*128*128,128,0, tb,NN,128L*NN, ub,NN,128L*NN, 128,NN,128, bt+il*128,0,0,0);
        stats_mean_k<<<128,256>>>(ub,128);
        stats_var_k<<<128,256>>>(ub,128);
        bn_relu_add_k<<<(BB*128*NN)/256,256>>>(ub, xin, xs, cat + (long)il*128*NN);
    }

    // ---- head ----
    bgemmT<8>(Wf,512,0, cat,NN,512L*NN, fuse,NN,1024L*NN, 1024,NN,512, bf,0,0,0);
    stats_mean_k<<<1024,256>>>(fuse,1024);
    stats_var_k<<<1024,256>>>(fuse,1024);
    bn_relu_k<<<(BB*1024*NN)/256,256>>>(fuse,fuse,1024);
    gmax_k<<<dim3(1024,BB),256>>>();
    c0_k<<<dim3(512,BB),256>>>(Wc1, bc1);
    bgemmT<8>(Wc1+1024,1536,0, cat,NN,512L*NN, h1,NN,512L*NN, 512,NN,512, 0,c0,0,0);
    stats_mean_k<<<512,256>>>(h1,512);
    stats_var_k<<<512,256>>>(h1,512);
    bn_relu_k<<<(BB*512*NN)/256,256>>>(h1,h1,512);
    bgemmT<4>(Wc2,512,0, h1,NN,512L*NN, h2,NN,256L*NN, 256,NN,512, bc2,0,0,0);
    stats_mean_k<<<256,256>>>(h2,256);
    stats_var_k<<<256,256>>>(h2,256);
    bn_relu_k<<<(BB*256*NN)/256,256>>>(h2,h2,256);
    sgemmT<1>(Wc3,256,0, h2,NN,256L*NN, out,NN,13L*NN, 13,NN,256, bc3,0,0,0);
}